// round 1
// baseline (speedup 1.0000x reference)
#include <cuda_runtime.h>
#include <math.h>

#define B_  4
#define N_  2048
#define D_  256
#define H_  4
#define E_  256
#define M_  (B_*N_)          // 8192 rows
#define HB_ (H_*B_)          // 16
#define PADV (-2.0f)
#define EPS_ 1e-6f

// ---------------- scratch (device globals; no runtime alloc) ----------------
__device__ float g_xn[(size_t)M_*D_];            // LN(x)
__device__ float g_q [(size_t)HB_*N_*E_];        // [H, B*N, E]
__device__ float g_k [(size_t)HB_*N_*E_];
__device__ float g_v [(size_t)HB_*N_*E_];
__device__ float g_gt[(size_t)HB_*N_*E_];        // gate pre-activation
__device__ float g_o [(size_t)HB_*N_*E_];        // attention output
__device__ float g_y [(size_t)M_*H_*E_];         // concat [B,N, e*H+h]
__device__ float g_z [(size_t)M_*E_];            // pre-final-LN

// ---------------- block LN helper (256 threads, 1 value/thread) -------------
__device__ __forceinline__ void block_meanvar(float v, float& mean, float& var) {
    float s = v, s2 = v * v;
    #pragma unroll
    for (int o = 16; o; o >>= 1) {
        s  += __shfl_xor_sync(0xffffffffu, s,  o);
        s2 += __shfl_xor_sync(0xffffffffu, s2, o);
    }
    __shared__ float ws[8], ws2[8];
    int w = threadIdx.x >> 5, l = threadIdx.x & 31;
    if (l == 0) { ws[w] = s; ws2[w] = s2; }
    __syncthreads();
    float ts = 0.f, ts2 = 0.f;
    #pragma unroll
    for (int i = 0; i < 8; i++) { ts += ws[i]; ts2 += ws2[i]; }
    mean = ts * (1.0f / 256.0f);
    var  = ts2 * (1.0f / 256.0f) - mean * mean;
    __syncthreads();   // allow helper reuse
}

// ---------------- K1: input LN ----------------------------------------------
__global__ void ln_in_k(const float* __restrict__ x,
                        const float* __restrict__ g, const float* __restrict__ b) {
    int m = blockIdx.x, e = threadIdx.x;
    float v = x[(size_t)m * D_ + e];
    float mean, var;
    block_meanvar(v, mean, var);
    g_xn[(size_t)m * D_ + e] = (v - mean) * rsqrtf(var + EPS_) * g[e] + b[e];
}

// ---------------- generic 64x64-tile fp32 GEMM (256 thr, 4x4/thread) --------
__device__ __forceinline__ void gemm_tile_64x64(
    const float* __restrict__ A, int ldA,
    const float* __restrict__ W, int ldW,
    int K, float acc[4][4], int m0, int n0)
{
    __shared__ float As[32 * 68];   // transposed: As[k][i]
    __shared__ float Ws[32 * 68];   // natural:    Ws[k][n]
    int tid = threadIdx.x, tx = tid & 15, ty = tid >> 4;

    #pragma unroll
    for (int r = 0; r < 4; r++)
        #pragma unroll
        for (int c = 0; c < 4; c++) acc[r][c] = 0.f;

    for (int k0 = 0; k0 < K; k0 += 32) {
        #pragma unroll
        for (int it = 0; it < 8; it++) {
            int idx = tid + it * 256;
            int i = idx >> 5, j = idx & 31;
            As[j * 68 + i] = A[(size_t)(m0 + i) * ldA + k0 + j];
        }
        #pragma unroll
        for (int it = 0; it < 8; it++) {
            int idx = tid + it * 256;
            int kk = idx >> 6, nn = idx & 63;
            Ws[kk * 68 + nn] = W[(size_t)(k0 + kk) * ldW + n0 + nn];
        }
        __syncthreads();
        #pragma unroll
        for (int kk = 0; kk < 32; kk++) {
            float4 a = *(const float4*)&As[kk * 68 + ty * 4];
            float4 w = *(const float4*)&Ws[kk * 68 + tx * 4];
            float av[4] = {a.x, a.y, a.z, a.w};
            float wv[4] = {w.x, w.y, w.z, w.w};
            #pragma unroll
            for (int r = 0; r < 4; r++)
                #pragma unroll
                for (int c = 0; c < 4; c++) acc[r][c] = fmaf(av[r], wv[c], acc[r][c]);
        }
        __syncthreads();
    }
}

// ---------------- K2: Q/K/V/gate projections (grid.z = h*4+t) ---------------
__global__ void __launch_bounds__(256) qkvg_k(
    const float* __restrict__ Wq, const float* __restrict__ Wk,
    const float* __restrict__ Wv, const float* __restrict__ Wg)
{
    int z = blockIdx.z, h = z >> 2, t = z & 3;
    const float* W = (t == 0 ? Wq : t == 1 ? Wk : t == 2 ? Wv : Wg) + (size_t)h * D_ * E_;
    float* C = (t == 0 ? g_q : t == 1 ? g_k : t == 2 ? g_v : g_gt) + (size_t)h * M_ * E_;
    int m0 = blockIdx.x * 64, n0 = blockIdx.y * 64;
    float acc[4][4];
    gemm_tile_64x64(g_xn, D_, W, E_, D_, acc, m0, n0);
    int tx = threadIdx.x & 15, ty = threadIdx.x >> 4;
    #pragma unroll
    for (int r = 0; r < 4; r++)
        #pragma unroll
        for (int c = 0; c < 4; c++)
            C[(size_t)(m0 + ty * 4 + r) * E_ + n0 + tx * 4 + c] = acc[r][c];
}

// ---------------- K3: flash attention (BM=BN=64) -----------------------------
__global__ void __launch_bounds__(256) attn_k(const float* __restrict__ mask)
{
    int qt = blockIdx.x;               // query tile 0..31
    int hb = blockIdx.y;               // h*B+b, 0..15
    int b  = hb & 3;
    const float* Q  = g_q + (size_t)hb * N_ * E_;
    const float* Kp = g_k + (size_t)hb * N_ * E_;
    const float* Vp = g_v + (size_t)hb * N_ * E_;
    float*       O  = g_o + (size_t)hb * N_ * E_;
    const float* mrow = mask + (size_t)b * N_;

    int tid = threadIdx.x, tx = tid & 15, ty = tid >> 4;
    int qbase = qt * 64;

    __shared__ float s_uni[64 * 68];   // QT(32x68)+KT(32x68) union PsT(64x68)
    __shared__ float s_vs [64 * 64];
    __shared__ float s_km [64];
    float* QT  = s_uni;
    float* KT  = s_uni + 32 * 68;
    float* PsT = s_uni;

    float acc[4][16];
    #pragma unroll
    for (int r = 0; r < 4; r++)
        #pragma unroll
        for (int c = 0; c < 16; c++) acc[r][c] = 0.f;
    float mrun[4] = {-1e30f, -1e30f, -1e30f, -1e30f};
    float lrun[4] = {0.f, 0.f, 0.f, 0.f};

    const float scale = 0.0625f;   // 1/sqrt(256)

    for (int kt = 0; kt < 32; kt++) {
        int kbase = kt * 64;
        if (tid < 64) s_km[tid] = (mrow[kbase + tid] == PADV) ? 0.f : 1.f;

        // ---- scores S = Q K^T over E=256 in chunks of 32 ----
        float sc[4][4];
        #pragma unroll
        for (int r = 0; r < 4; r++)
            #pragma unroll
            for (int c = 0; c < 4; c++) sc[r][c] = 0.f;

        for (int kc = 0; kc < 8; kc++) {
            __syncthreads();   // protect s_uni from prior readers
            #pragma unroll
            for (int it = 0; it < 8; it++) {
                int idx = tid + it * 256;
                int i = idx >> 5, j = idx & 31;
                QT[j * 68 + i] = Q [(size_t)(qbase + i) * E_ + kc * 32 + j];
                KT[j * 68 + i] = Kp[(size_t)(kbase + i) * E_ + kc * 32 + j];
            }
            __syncthreads();
            #pragma unroll
            for (int kk = 0; kk < 32; kk++) {
                float4 qa = *(const float4*)&QT[kk * 68 + ty * 4];
                float4 kb = *(const float4*)&KT[kk * 68 + tx * 4];
                float qv[4] = {qa.x, qa.y, qa.z, qa.w};
                float kv[4] = {kb.x, kb.y, kb.z, kb.w};
                #pragma unroll
                for (int r = 0; r < 4; r++)
                    #pragma unroll
                    for (int c = 0; c < 4; c++) sc[r][c] = fmaf(qv[r], kv[c], sc[r][c]);
            }
        }
        __syncthreads();   // all reads of QT/KT done before PsT writes

        // ---- online softmax update ----
        float kval[4];
        #pragma unroll
        for (int c = 0; c < 4; c++) kval[c] = s_km[tx * 4 + c];

        float ps[4][4];
        #pragma unroll
        for (int r = 0; r < 4; r++) {
            float tm = -1e30f;
            #pragma unroll
            for (int c = 0; c < 4; c++) {
                float sv = (kval[c] > 0.f) ? sc[r][c] * scale : -1e30f;
                sc[r][c] = sv;
                tm = fmaxf(tm, sv);
            }
            #pragma unroll
            for (int o = 8; o; o >>= 1) tm = fmaxf(tm, __shfl_xor_sync(0xffffffffu, tm, o));
            float mnew = fmaxf(mrun[r], tm);
            float corr = __expf(mrun[r] - mnew);
            float rs = 0.f;
            #pragma unroll
            for (int c = 0; c < 4; c++) {
                float p = (kval[c] > 0.f) ? __expf(sc[r][c] - mnew) : 0.f;
                ps[r][c] = p;
                rs += p;
            }
            #pragma unroll
            for (int o = 8; o; o >>= 1) rs += __shfl_xor_sync(0xffffffffu, rs, o);
            lrun[r] = lrun[r] * corr + rs;
            mrun[r] = mnew;
            #pragma unroll
            for (int c = 0; c < 16; c++) acc[r][c] *= corr;
        }

        // ---- write P (transposed) ----
        #pragma unroll
        for (int c = 0; c < 4; c++)
            #pragma unroll
            for (int r = 0; r < 4; r++)
                PsT[(tx * 4 + c) * 68 + ty * 4 + r] = ps[r][c];
        __syncthreads();

        // ---- O += P @ V, in 4 chunks of 64 columns ----
        for (int ec = 0; ec < 4; ec++) {
            #pragma unroll
            for (int it = 0; it < 16; it++) {
                int idx = tid + it * 256;
                int j = idx >> 6, e = idx & 63;
                s_vs[j * 64 + e] = Vp[(size_t)(kbase + j) * E_ + ec * 64 + e];
            }
            __syncthreads();
            #pragma unroll 4
            for (int j = 0; j < 64; j++) {
                float4 pv = *(const float4*)&PsT[j * 68 + ty * 4];
                float4 vv = *(const float4*)&s_vs[j * 64 + tx * 4];
                float pr[4] = {pv.x, pv.y, pv.z, pv.w};
                float vr[4] = {vv.x, vv.y, vv.z, vv.w};
                #pragma unroll
                for (int r = 0; r < 4; r++)
                    #pragma unroll
                    for (int c = 0; c < 4; c++)
                        acc[r][ec * 4 + c] = fmaf(pr[r], vr[c], acc[r][ec * 4 + c]);
            }
            __syncthreads();
        }
    }

    // ---- finalize ----
    #pragma unroll
    for (int r = 0; r < 4; r++) {
        int qrow = qbase + ty * 4 + r;
        float qm = (mrow[qrow] == PADV) ? 0.f : 1.f;
        float inv = qm / fmaxf(lrun[r], 1e-30f);
        #pragma unroll
        for (int ec = 0; ec < 4; ec++)
            #pragma unroll
            for (int c = 0; c < 4; c++)
                O[(size_t)qrow * E_ + ec * 64 + tx * 4 + c] = acc[r][ec * 4 + c] * inv;
    }
}

// ---------------- K4: gate + residual + per-head LN + concat ----------------
__global__ void epi_k(const float* __restrict__ x,
                      const float* __restrict__ gr, const float* __restrict__ br)
{
    int m = blockIdx.x, e = threadIdx.x;
    float xv = x[(size_t)m * D_ + e];
    for (int h = 0; h < H_; h++) {
        size_t off = ((size_t)h * M_ + m) * E_ + e;
        float ov = g_o[off];
        float gv = g_gt[off];
        float sg = 1.f / (1.f + __expf(-gv));
        float t  = ov * sg + xv;
        float mean, var;
        block_meanvar(t, mean, var);
        float yn = (t - mean) * rsqrtf(var + EPS_) * gr[e] + br[e];
        g_y[(size_t)m * (H_ * E_) + e * H_ + h] = yn;
    }
}

// ---------------- K5: output projection + bias + residual -------------------
__global__ void __launch_bounds__(256) outproj_k(
    const float* __restrict__ out_w, const float* __restrict__ out_b,
    const float* __restrict__ x)
{
    int m0 = blockIdx.x * 64, n0 = blockIdx.y * 64;
    float acc[4][4];
    gemm_tile_64x64(g_y, H_ * E_, out_w, E_, H_ * E_, acc, m0, n0);
    int tx = threadIdx.x & 15, ty = threadIdx.x >> 4;
    #pragma unroll
    for (int r = 0; r < 4; r++) {
        int m = m0 + ty * 4 + r;
        #pragma unroll
        for (int c = 0; c < 4; c++) {
            int n = n0 + tx * 4 + c;
            g_z[(size_t)m * E_ + n] = acc[r][c] + out_b[n] + x[(size_t)m * D_ + n];
        }
    }
}

// ---------------- K6: final LN * mask ----------------------------------------
__global__ void final_k(const float* __restrict__ mask,
                        const float* __restrict__ go, const float* __restrict__ bo,
                        float* __restrict__ out)
{
    int m = blockIdx.x, e = threadIdx.x;
    float v = g_z[(size_t)m * E_ + e];
    float mean, var;
    block_meanvar(v, mean, var);
    float mv = (mask[m] == PADV) ? 0.f : 1.f;
    out[(size_t)m * E_ + e] = ((v - mean) * rsqrtf(var + EPS_) * go[e] + bo[e]) * mv;
}

// ---------------- launch ------------------------------------------------------
extern "C" void kernel_launch(void* const* d_in, const int* in_sizes, int n_in,
                              void* d_out, int out_size)
{
    const float* x     = (const float*)d_in[0];
    const float* mask  = (const float*)d_in[1];
    const float* Wq    = (const float*)d_in[2];
    const float* Wk    = (const float*)d_in[3];
    const float* Wv    = (const float*)d_in[4];
    const float* Wg    = (const float*)d_in[5];
    const float* out_w = (const float*)d_in[6];
    const float* out_b = (const float*)d_in[7];
    const float* g_in  = (const float*)d_in[8];
    const float* b_in  = (const float*)d_in[9];
    const float* g_res = (const float*)d_in[10];
    const float* b_res = (const float*)d_in[11];
    const float* g_out = (const float*)d_in[12];
    const float* b_out = (const float*)d_in[13];
    float* out = (float*)d_out;

    ln_in_k<<<M_, 256>>>(x, g_in, b_in);

    dim3 g2(M_ / 64, E_ / 64, HB_);            // (128, 4, 16)
    qkvg_k<<<g2, 256>>>(Wq, Wk, Wv, Wg);

    dim3 g3(N_ / 64, HB_);                     // (32, 16)
    attn_k<<<g3, 256>>>(mask);

    epi_k<<<M_, 256>>>(x, g_res, b_res);

    dim3 g5(M_ / 64, E_ / 64);                 // (128, 4)
    outproj_k<<<g5, 256>>>(out_w, out_b, x);

    final_k<<<M_, 256>>>(mask, g_out, b_out, out);
}

// round 3
// speedup vs baseline: 3.2419x; 3.2419x over previous
#include <cuda_runtime.h>
#include <cuda_fp16.h>
#include <math.h>
#include <stdint.h>

#define B_  4
#define N_  2048
#define D_  256
#define H_  4
#define E_  256
#define M_  (B_*N_)          // 8192 rows
#define HB_ (H_*B_)          // 16
#define PADV (-2.0f)
#define EPS_ 1e-6f
#define SCALE_ 0.0625f       // 1/sqrt(256)

// ---------------- scratch (device globals; no runtime alloc) ----------------
__device__ float  g_xn[(size_t)M_*D_];           // LN(x)
__device__ __half g_qh[(size_t)HB_*N_*E_];       // Q fp16 [h][m][e]
__device__ __half g_kh[(size_t)HB_*N_*E_];       // K fp16 [h][m][e]
__device__ __half g_vt[(size_t)HB_*E_*N_];       // V^T fp16 [h][b][e][n]
__device__ float  g_gt[(size_t)HB_*N_*E_];       // gate pre-activation
__device__ float  g_o [(size_t)HB_*N_*E_];       // attention output
__device__ float  g_y [(size_t)M_*H_*E_];        // concat [B,N, e*H+h]
__device__ float  g_z [(size_t)M_*E_];           // pre-final-LN

// =================== PTX helpers (compute_103-safe) ===================
__device__ __forceinline__ uint32_t s2u(const void* p){
    uint32_t a;
    asm("{ .reg .u64 t; cvta.to.shared.u64 t, %1; cvt.u32.u64 %0, t; }" : "=r"(a) : "l"(p));
    return a;
}
__device__ __forceinline__ void cp16(uint32_t s, const void* g){
    asm volatile("cp.async.cg.shared.global [%0], [%1], 16;" :: "r"(s), "l"(g));
}
__device__ __forceinline__ void cp_commit(){ asm volatile("cp.async.commit_group;" ::: "memory"); }
template<int NN> __device__ __forceinline__ void cp_wait(){
    asm volatile("cp.async.wait_group %0;" :: "n"(NN) : "memory");
}
__device__ __forceinline__ void ldsm_x4(uint32_t& r0, uint32_t& r1, uint32_t& r2, uint32_t& r3, uint32_t addr){
    asm volatile("ldmatrix.sync.aligned.m8n8.x4.shared.b16 {%0,%1,%2,%3}, [%4];"
        : "=r"(r0), "=r"(r1), "=r"(r2), "=r"(r3) : "r"(addr));
}
__device__ __forceinline__ void mma16816(float c[4], uint32_t a0, uint32_t a1, uint32_t a2, uint32_t a3,
                                         uint32_t b0, uint32_t b1){
    asm volatile("mma.sync.aligned.m16n8k16.row.col.f32.f16.f16.f32 "
        "{%0,%1,%2,%3}, {%4,%5,%6,%7}, {%8,%9}, {%0,%1,%2,%3};"
        : "+f"(c[0]), "+f"(c[1]), "+f"(c[2]), "+f"(c[3])
        : "r"(a0), "r"(a1), "r"(a2), "r"(a3), "r"(b0), "r"(b1));
}

// ---------------- block LN helper (256 threads, 1 value/thread) -------------
__device__ __forceinline__ void block_meanvar(float v, float& mean, float& var) {
    float s = v, s2 = v * v;
    #pragma unroll
    for (int o = 16; o; o >>= 1) {
        s  += __shfl_xor_sync(0xffffffffu, s,  o);
        s2 += __shfl_xor_sync(0xffffffffu, s2, o);
    }
    __shared__ float ws[8], ws2[8];
    int w = threadIdx.x >> 5, l = threadIdx.x & 31;
    if (l == 0) { ws[w] = s; ws2[w] = s2; }
    __syncthreads();
    float ts = 0.f, ts2 = 0.f;
    #pragma unroll
    for (int i = 0; i < 8; i++) { ts += ws[i]; ts2 += ws2[i]; }
    mean = ts * (1.0f / 256.0f);
    var  = ts2 * (1.0f / 256.0f) - mean * mean;
    __syncthreads();
}

// ---------------- K1: input LN ----------------------------------------------
__global__ void ln_in_k(const float* __restrict__ x,
                        const float* __restrict__ g, const float* __restrict__ b) {
    int m = blockIdx.x, e = threadIdx.x;
    float v = x[(size_t)m * D_ + e];
    float mean, var;
    block_meanvar(v, mean, var);
    g_xn[(size_t)m * D_ + e] = (v - mean) * rsqrtf(var + EPS_) * g[e] + b[e];
}

// ---------------- generic 64x64-tile fp32 GEMM (256 thr, 4x4/thread) --------
__device__ __forceinline__ void gemm_tile_64x64(
    const float* __restrict__ A, int ldA,
    const float* __restrict__ W, int ldW,
    int K, float acc[4][4], int m0, int n0)
{
    __shared__ float As[32 * 68];
    __shared__ float Ws[32 * 68];
    int tid = threadIdx.x, tx = tid & 15, ty = tid >> 4;

    #pragma unroll
    for (int r = 0; r < 4; r++)
        #pragma unroll
        for (int c = 0; c < 4; c++) acc[r][c] = 0.f;

    for (int k0 = 0; k0 < K; k0 += 32) {
        #pragma unroll
        for (int it = 0; it < 8; it++) {
            int idx = tid + it * 256;
            int i = idx >> 5, j = idx & 31;
            As[j * 68 + i] = A[(size_t)(m0 + i) * ldA + k0 + j];
        }
        #pragma unroll
        for (int it = 0; it < 8; it++) {
            int idx = tid + it * 256;
            int kk = idx >> 6, nn = idx & 63;
            Ws[kk * 68 + nn] = W[(size_t)(k0 + kk) * ldW + n0 + nn];
        }
        __syncthreads();
        #pragma unroll
        for (int kk = 0; kk < 32; kk++) {
            float4 a = *(const float4*)&As[kk * 68 + ty * 4];
            float4 w = *(const float4*)&Ws[kk * 68 + tx * 4];
            float av[4] = {a.x, a.y, a.z, a.w};
            float wv[4] = {w.x, w.y, w.z, w.w};
            #pragma unroll
            for (int r = 0; r < 4; r++)
                #pragma unroll
                for (int c = 0; c < 4; c++) acc[r][c] = fmaf(av[r], wv[c], acc[r][c]);
        }
        __syncthreads();
    }
}

// ---------------- K2: Q/K/V/gate projections (grid.z = h*4+t) ---------------
__global__ void __launch_bounds__(256) qkvg_k(
    const float* __restrict__ Wq, const float* __restrict__ Wk,
    const float* __restrict__ Wv, const float* __restrict__ Wg)
{
    int z = blockIdx.z, h = z >> 2, t = z & 3;
    const float* W = (t == 0 ? Wq : t == 1 ? Wk : t == 2 ? Wv : Wg) + (size_t)h * D_ * E_;
    int m0 = blockIdx.x * 64, n0 = blockIdx.y * 64;
    float acc[4][4];
    gemm_tile_64x64(g_xn, D_, W, E_, D_, acc, m0, n0);
    int tx = threadIdx.x & 15, ty = threadIdx.x >> 4;
    if (t < 2) {
        __half* C = (t == 0 ? g_qh : g_kh) + (size_t)h * M_ * E_;
        #pragma unroll
        for (int r = 0; r < 4; r++)
            #pragma unroll
            for (int c = 0; c < 4; c++)
                C[(size_t)(m0 + ty * 4 + r) * E_ + n0 + tx * 4 + c] = __float2half_rn(acc[r][c]);
    } else if (t == 2) {
        // V transposed: g_vt[h][b][e][n]
        #pragma unroll
        for (int r = 0; r < 4; r++) {
            int m = m0 + ty * 4 + r;
            int bidx = m >> 11, n = m & (N_ - 1);
            size_t base = (size_t)(h * B_ + bidx) * E_;
            #pragma unroll
            for (int c = 0; c < 4; c++)
                g_vt[(base + n0 + tx * 4 + c) * N_ + n] = __float2half_rn(acc[r][c]);
        }
    } else {
        float* C = g_gt + (size_t)h * M_ * E_;
        #pragma unroll
        for (int r = 0; r < 4; r++)
            #pragma unroll
            for (int c = 0; c < 4; c++)
                C[(size_t)(m0 + ty * 4 + r) * E_ + n0 + tx * 4 + c] = acc[r][c];
    }
}

// =================== K3: HMMA flash attention =================================
// SMEM: Q[128][264] fp16 + K[2][64][264] fp16 + VT[2][256][72] fp16
#define LDK 264
#define LDV 72
#define SM_Q   0
#define SM_K   (128 * LDK)                 // halves
#define SM_V   (SM_K + 2 * 64 * LDK)
#define SMEM_H (SM_V + 2 * 256 * LDV)      // total halves
#define SMEM_TOT (SMEM_H * 2)              // bytes = 208896

__global__ void __launch_bounds__(256, 1) attn_mma_k(const float* __restrict__ mask)
{
    extern __shared__ __half sm[];
    const int tid = threadIdx.x, lane = tid & 31, warp = tid >> 5;
    const int qt = blockIdx.x, hb = blockIdx.y, bidx = hb & (B_ - 1);
    const int qbase = qt * 128;
    const __half* Qg = g_qh + (size_t)hb * N_ * E_ + (size_t)qbase * E_;
    const __half* Kg = g_kh + (size_t)hb * N_ * E_;
    const __half* Vt = g_vt + (size_t)hb * E_ * N_;
    float* Og = g_o + (size_t)hb * N_ * E_;
    const float* mrow = mask + (size_t)bidx * N_;

    const uint32_t sQ = s2u(sm + SM_Q);
    const uint32_t sK = s2u(sm + SM_K);
    const uint32_t sV = s2u(sm + SM_V);

    // ---- prologue: Q + chunk0 (group 0), chunk1 (group 1) ----
    #pragma unroll
    for (int it = 0; it < 16; it++) {
        int idx = tid + it * 256;
        int row = idx >> 5, c = idx & 31;
        cp16(sQ + (uint32_t)(row * LDK + c * 8) * 2, Qg + (size_t)row * E_ + c * 8);
    }
    #pragma unroll
    for (int buf = 0; buf < 2; buf++) {
        #pragma unroll
        for (int it = 0; it < 8; it++) {
            int idx = tid + it * 256;
            int row = idx >> 5, c = idx & 31;
            cp16(sK + (uint32_t)(buf * 64 * LDK + row * LDK + c * 8) * 2,
                 Kg + (size_t)(buf * 64 + row) * E_ + c * 8);
        }
        #pragma unroll
        for (int it = 0; it < 8; it++) {
            int idx = tid + it * 256;
            int e = idx >> 3, c = idx & 7;
            cp16(sV + (uint32_t)(buf * 256 * LDV + e * LDV + c * 8) * 2,
                 Vt + (size_t)e * N_ + buf * 64 + c * 8);
        }
        cp_commit();
    }

    // per-lane ldmatrix base addresses
    const int grp = lane >> 3, r8 = lane & 7;
    const int moff = (grp & 2) ? 8 : 0;    // +8 rows for matrices 2,3
    const int koff = (grp & 1) ? 8 : 0;    // +8 k for matrices 1,3
    const uint32_t qaddr0 = sQ + (uint32_t)((warp * 16 + (lane & 15)) * LDK + (lane >> 4) * 8) * 2;
    const uint32_t kaddr0 = sK + (uint32_t)((moff + r8) * LDK + koff) * 2;
    const uint32_t vaddr0 = sV + (uint32_t)((moff + r8) * LDV + koff) * 2;

    float O[32][4];
    #pragma unroll
    for (int i = 0; i < 32; i++)
        #pragma unroll
        for (int j = 0; j < 4; j++) O[i][j] = 0.f;
    float l0 = 0.f, l1 = 0.f;

    for (int kc = 0; kc < 32; kc++) {
        if (kc == 31) cp_wait<0>(); else cp_wait<1>();
        __syncthreads();
        const int kb = kc * 64;
        const uint32_t kbuf = kaddr0 + (uint32_t)((kc & 1) * 64 * LDK) * 2;
        const uint32_t vbuf = vaddr0 + (uint32_t)((kc & 1) * 256 * LDV) * 2;

        // ---- S = Q K^T : 8 n-blocks x 16 k-steps ----
        float S[8][4];
        #pragma unroll
        for (int i = 0; i < 8; i++)
            #pragma unroll
            for (int j = 0; j < 4; j++) S[i][j] = 0.f;

        #pragma unroll
        for (int ks = 0; ks < 16; ks++) {
            uint32_t q0, q1, q2, q3;
            ldsm_x4(q0, q1, q2, q3, qaddr0 + (uint32_t)(ks * 32));
            #pragma unroll
            for (int nbp = 0; nbp < 4; nbp++) {
                uint32_t b0, b1, b2, b3;
                ldsm_x4(b0, b1, b2, b3, kbuf + (uint32_t)(nbp * 16 * LDK * 2 + ks * 32));
                mma16816(S[2 * nbp],     q0, q1, q2, q3, b0, b1);
                mma16816(S[2 * nbp + 1], q0, q1, q2, q3, b2, b3);
            }
        }

        // ---- softmax: P = exp(S*scale) * keymask ; A-fragments for PV ----
        uint32_t pa[4][4];
        #pragma unroll
        for (int nb = 0; nb < 8; nb++) {
            int cb = kb + nb * 8 + (lane & 3) * 2;
            float km0 = (__ldg(mrow + cb)     == PADV) ? 0.f : 1.f;
            float km1 = (__ldg(mrow + cb + 1) == PADV) ? 0.f : 1.f;
            float p0 = __expf(S[nb][0] * SCALE_) * km0;
            float p1 = __expf(S[nb][1] * SCALE_) * km1;
            float p2 = __expf(S[nb][2] * SCALE_) * km0;
            float p3 = __expf(S[nb][3] * SCALE_) * km1;
            l0 += p0 + p1;
            l1 += p2 + p3;
            __half2 h01 = __floats2half2_rn(p0, p1);
            __half2 h23 = __floats2half2_rn(p2, p3);
            pa[nb >> 1][(nb & 1) * 2]     = *(uint32_t*)&h01;
            pa[nb >> 1][(nb & 1) * 2 + 1] = *(uint32_t*)&h23;
        }

        // ---- O += P V : 32 e-blocks x 4 k-steps ----
        #pragma unroll
        for (int ebp = 0; ebp < 16; ebp++) {
            #pragma unroll
            for (int ks = 0; ks < 4; ks++) {
                uint32_t v0, v1, v2, v3;
                ldsm_x4(v0, v1, v2, v3, vbuf + (uint32_t)(ebp * 16 * LDV * 2 + ks * 32));
                mma16816(O[2 * ebp],     pa[ks][0], pa[ks][1], pa[ks][2], pa[ks][3], v0, v1);
                mma16816(O[2 * ebp + 1], pa[ks][0], pa[ks][1], pa[ks][2], pa[ks][3], v2, v3);
            }
        }

        __syncthreads();
        // prefetch chunk kc+2 into buffer (kc&1)
        if (kc + 2 < 32) {
            const int nb2 = kb + 128;
            #pragma unroll
            for (int it = 0; it < 8; it++) {
                int idx = tid + it * 256;
                int row = idx >> 5, c = idx & 31;
                cp16(sK + (uint32_t)((kc & 1) * 64 * LDK + row * LDK + c * 8) * 2,
                     Kg + (size_t)(nb2 + row) * E_ + c * 8);
            }
            #pragma unroll
            for (int it = 0; it < 8; it++) {
                int idx = tid + it * 256;
                int e = idx >> 3, c = idx & 7;
                cp16(sV + (uint32_t)((kc & 1) * 256 * LDV + e * LDV + c * 8) * 2,
                     Vt + (size_t)e * N_ + nb2 + c * 8);
            }
            cp_commit();
        }
    }

    // ---- finalize: reduce row sums across quad, normalize, write ----
    l0 += __shfl_xor_sync(0xffffffffu, l0, 1);
    l0 += __shfl_xor_sync(0xffffffffu, l0, 2);
    l1 += __shfl_xor_sync(0xffffffffu, l1, 1);
    l1 += __shfl_xor_sync(0xffffffffu, l1, 2);
    const int r0 = qbase + warp * 16 + (lane >> 2);
    const int r1 = r0 + 8;
    float inv0 = ((mrow[r0] == PADV) ? 0.f : 1.f) / fmaxf(l0, 1e-30f);
    float inv1 = ((mrow[r1] == PADV) ? 0.f : 1.f) / fmaxf(l1, 1e-30f);
    #pragma unroll
    for (int eb = 0; eb < 32; eb++) {
        int col = eb * 8 + (lane & 3) * 2;
        *(float2*)&Og[(size_t)r0 * E_ + col] = make_float2(O[eb][0] * inv0, O[eb][1] * inv0);
        *(float2*)&Og[(size_t)r1 * E_ + col] = make_float2(O[eb][2] * inv1, O[eb][3] * inv1);
    }
}

// ---------------- K4: gate + residual + per-head LN + concat ----------------
__global__ void epi_k(const float* __restrict__ x,
                      const float* __restrict__ gr, const float* __restrict__ br)
{
    int m = blockIdx.x, e = threadIdx.x;
    float xv = x[(size_t)m * D_ + e];
    for (int h = 0; h < H_; h++) {
        size_t off = ((size_t)h * M_ + m) * E_ + e;
        float ov = g_o[off];
        float gv = g_gt[off];
        float sg = 1.f / (1.f + __expf(-gv));
        float t  = ov * sg + xv;
        float mean, var;
        block_meanvar(t, mean, var);
        float yn = (t - mean) * rsqrtf(var + EPS_) * gr[e] + br[e];
        g_y[(size_t)m * (H_ * E_) + e * H_ + h] = yn;
    }
}

// ---------------- K5: output projection + bias + residual -------------------
__global__ void __launch_bounds__(256) outproj_k(
    const float* __restrict__ out_w, const float* __restrict__ out_b,
    const float* __restrict__ x)
{
    int m0 = blockIdx.x * 64, n0 = blockIdx.y * 64;
    float acc[4][4];
    gemm_tile_64x64(g_y, H_ * E_, out_w, E_, H_ * E_, acc, m0, n0);
    int tx = threadIdx.x & 15, ty = threadIdx.x >> 4;
    #pragma unroll
    for (int r = 0; r < 4; r++) {
        int m = m0 + ty * 4 + r;
        #pragma unroll
        for (int c = 0; c < 4; c++) {
            int n = n0 + tx * 4 + c;
            g_z[(size_t)m * E_ + n] = acc[r][c] + out_b[n] + x[(size_t)m * D_ + n];
        }
    }
}

// ---------------- K6: final LN * mask ----------------------------------------
__global__ void final_k(const float* __restrict__ mask,
                        const float* __restrict__ go, const float* __restrict__ bo,
                        float* __restrict__ out)
{
    int m = blockIdx.x, e = threadIdx.x;
    float v = g_z[(size_t)m * E_ + e];
    float mean, var;
    block_meanvar(v, mean, var);
    float mv = (mask[m] == PADV) ? 0.f : 1.f;
    out[(size_t)m * E_ + e] = ((v - mean) * rsqrtf(var + EPS_) * go[e] + bo[e]) * mv;
}

// ---------------- launch ------------------------------------------------------
extern "C" void kernel_launch(void* const* d_in, const int* in_sizes, int n_in,
                              void* d_out, int out_size)
{
    (void)in_sizes; (void)n_in; (void)out_size;
    const float* x     = (const float*)d_in[0];
    const float* mask  = (const float*)d_in[1];
    const float* Wq    = (const float*)d_in[2];
    const float* Wk    = (const float*)d_in[3];
    const float* Wv    = (const float*)d_in[4];
    const float* Wg    = (const float*)d_in[5];
    const float* out_w = (const float*)d_in[6];
    const float* out_b = (const float*)d_in[7];
    const float* g_in  = (const float*)d_in[8];
    const float* b_in  = (const float*)d_in[9];
    const float* g_res = (const float*)d_in[10];
    const float* b_res = (const float*)d_in[11];
    const float* g_out = (const float*)d_in[12];
    const float* b_out = (const float*)d_in[13];
    float* out = (float*)d_out;

    cudaFuncSetAttribute(attn_mma_k, cudaFuncAttributeMaxDynamicSharedMemorySize, SMEM_TOT);

    ln_in_k<<<M_, 256>>>(x, g_in, b_in);

    dim3 g2(M_ / 64, E_ / 64, HB_);            // (128, 4, 16)
    qkvg_k<<<g2, 256>>>(Wq, Wk, Wv, Wg);

    dim3 g3(N_ / 128, HB_);                    // (16, 16)
    attn_mma_k<<<g3, 256, SMEM_TOT>>>(mask);

    epi_k<<<M_, 256>>>(x, g_res, b_res);

    dim3 g5(M_ / 64, E_ / 64);                 // (128, 4)
    outproj_k<<<g5, 256>>>(out_w, out_b, x);

    final_k<<<M_, 256>>>(mask, g_out, b_out, out);
}

// round 4
// speedup vs baseline: 7.8459x; 2.4201x over previous
#include <cuda_runtime.h>
#include <cuda_fp16.h>
#include <math.h>
#include <stdint.h>

#define B_  4
#define N_  2048
#define D_  256
#define H_  4
#define E_  256
#define M_  (B_*N_)          // 8192 rows
#define HB_ (H_*B_)          // 16
#define PADV (-2.0f)
#define EPS_ 1e-6f
#define SCALE_ 0.0625f       // 1/sqrt(256)

// ---------------- scratch (device globals; no runtime alloc) ----------------
__device__ __half g_xnh[(size_t)M_*D_];          // LN(x) fp16
__device__ __half g_qh [(size_t)HB_*N_*E_];      // Q fp16 [h][m][e]
__device__ __half g_kh [(size_t)HB_*N_*E_];      // K fp16 [h][m][e]
__device__ __half g_vt [(size_t)HB_*E_*N_];      // V^T fp16 [h][b][e][n]
__device__ __half g_gth[(size_t)HB_*N_*E_];      // gate pre-activation fp16
__device__ __half g_oh [(size_t)HB_*N_*E_];      // attention output fp16
__device__ __half g_yh [(size_t)M_*H_*E_];       // concat fp16 [m][e*H+h]
__device__ float  g_z  [(size_t)M_*E_];          // pre-final-LN fp32
__device__ __half g_wh [(size_t)4*H_*D_*E_];     // qkvg weights fp16 [t][h][d][e]
__device__ __half g_w1h[(size_t)H_*E_*E_];       // out_w fp16 [1024][256]

// =================== PTX helpers (compute_103-safe) ===================
__device__ __forceinline__ uint32_t s2u(const void* p){
    uint32_t a;
    asm("{ .reg .u64 t; cvta.to.shared.u64 t, %1; cvt.u32.u64 %0, t; }" : "=r"(a) : "l"(p));
    return a;
}
__device__ __forceinline__ void cp16(uint32_t s, const void* g){
    asm volatile("cp.async.cg.shared.global [%0], [%1], 16;" :: "r"(s), "l"(g));
}
__device__ __forceinline__ void cp_commit(){ asm volatile("cp.async.commit_group;" ::: "memory"); }
template<int NN> __device__ __forceinline__ void cp_wait(){
    asm volatile("cp.async.wait_group %0;" :: "n"(NN) : "memory");
}
__device__ __forceinline__ void ldsm_x4(uint32_t& r0, uint32_t& r1, uint32_t& r2, uint32_t& r3, uint32_t addr){
    asm volatile("ldmatrix.sync.aligned.m8n8.x4.shared.b16 {%0,%1,%2,%3}, [%4];"
        : "=r"(r0), "=r"(r1), "=r"(r2), "=r"(r3) : "r"(addr));
}
__device__ __forceinline__ void ldsm_x4t(uint32_t& r0, uint32_t& r1, uint32_t& r2, uint32_t& r3, uint32_t addr){
    asm volatile("ldmatrix.sync.aligned.m8n8.x4.trans.shared.b16 {%0,%1,%2,%3}, [%4];"
        : "=r"(r0), "=r"(r1), "=r"(r2), "=r"(r3) : "r"(addr));
}
__device__ __forceinline__ void mma16816(float c[4], uint32_t a0, uint32_t a1, uint32_t a2, uint32_t a3,
                                         uint32_t b0, uint32_t b1){
    asm volatile("mma.sync.aligned.m16n8k16.row.col.f32.f16.f16.f32 "
        "{%0,%1,%2,%3}, {%4,%5,%6,%7}, {%8,%9}, {%0,%1,%2,%3};"
        : "+f"(c[0]), "+f"(c[1]), "+f"(c[2]), "+f"(c[3])
        : "r"(a0), "r"(a1), "r"(a2), "r"(a3), "r"(b0), "r"(b1));
}

// ---------------- block LN helper (256 threads, 1 value/thread) -------------
__device__ __forceinline__ void block_meanvar(float v, float& mean, float& var) {
    float s = v, s2 = v * v;
    #pragma unroll
    for (int o = 16; o; o >>= 1) {
        s  += __shfl_xor_sync(0xffffffffu, s,  o);
        s2 += __shfl_xor_sync(0xffffffffu, s2, o);
    }
    __shared__ float ws[8], ws2[8];
    int w = threadIdx.x >> 5, l = threadIdx.x & 31;
    if (l == 0) { ws[w] = s; ws2[w] = s2; }
    __syncthreads();
    float ts = 0.f, ts2 = 0.f;
    #pragma unroll
    for (int i = 0; i < 8; i++) { ts += ws[i]; ts2 += ws2[i]; }
    mean = ts * (1.0f / 256.0f);
    var  = ts2 * (1.0f / 256.0f) - mean * mean;
    __syncthreads();
}

// ---------------- K1: input LN (fp16 out) ------------------------------------
__global__ void ln_in_k(const float* __restrict__ x,
                        const float* __restrict__ g, const float* __restrict__ b) {
    int m = blockIdx.x, e = threadIdx.x;
    float v = x[(size_t)m * D_ + e];
    float mean, var;
    block_meanvar(v, mean, var);
    g_xnh[(size_t)m * D_ + e] = __float2half_rn((v - mean) * rsqrtf(var + EPS_) * g[e] + b[e]);
}

// ---------------- K1b: weight conversion fp32 -> fp16 -----------------------
__global__ void wconv_k(const float* __restrict__ Wq, const float* __restrict__ Wk,
                        const float* __restrict__ Wv, const float* __restrict__ Wg,
                        const float* __restrict__ ow) {
    int t = blockIdx.y;
    const float* src = (t == 0) ? Wq : (t == 1) ? Wk : (t == 2) ? Wv : (t == 3) ? Wg : ow;
    __half* dst = (t < 4) ? (g_wh + (size_t)t * (H_ * D_ * E_)) : g_w1h;
    int idx = (blockIdx.x * 256 + threadIdx.x) * 4;
    float4 v = *(const float4*)(src + idx);
    __half2* d2 = (__half2*)(dst + idx);
    d2[0] = __floats2half2_rn(v.x, v.y);
    d2[1] = __floats2half2_rn(v.z, v.w);
}

// =================== HMMA GEMM mainloop: 128 x 256 tile =======================
// SMEM: As[2][128][72] + Bs[2][64][264] halves = 104448 bytes
#define HG_LDA 72
#define HG_LDB 264
#define HG_BS_OFF 36864
#define HG_SMEM 104448
#define VT_LDT 136          // staging stride (halves) for transposed store

__device__ __forceinline__ void hg_load(const __half* A, int ldA, const __half* Bg,
                                        uint32_t sA, uint32_t sB, int c, int buf, int tid){
    #pragma unroll
    for (int it = 0; it < 4; it++){
        int idx = tid + it * 256;
        int row = idx >> 3, cg = idx & 7;
        cp16(sA + (uint32_t)(buf * 128 * HG_LDA + row * HG_LDA + cg * 8) * 2,
             A + (size_t)row * ldA + c * 64 + cg * 8);
    }
    #pragma unroll
    for (int it = 0; it < 8; it++){
        int idx = tid + it * 256;
        int row = idx >> 5, cg = idx & 31;
        cp16(sB + (uint32_t)(buf * 64 * HG_LDB + row * HG_LDB + cg * 8) * 2,
             Bg + (size_t)(c * 64 + row) * 256 + cg * 8);
    }
    cp_commit();
}

__device__ __forceinline__ void hgemm_main(const __half* A, int ldA, const __half* Bg,
                                           int NC, char* smem, float acc[32][4]){
    const int tid = threadIdx.x, lane = tid & 31, warp = tid >> 5;
    const uint32_t sA = s2u(smem), sB = s2u(smem + HG_BS_OFF);
    #pragma unroll
    for (int i = 0; i < 32; i++)
        #pragma unroll
        for (int j = 0; j < 4; j++) acc[i][j] = 0.f;

    hg_load(A, ldA, Bg, sA, sB, 0, 0, tid);
    hg_load(A, ldA, Bg, sA, sB, 1, 1, tid);

    const int grp = lane >> 3, r8 = lane & 7;
    const uint32_t aoff = (uint32_t)((warp * 16 + (lane & 15)) * HG_LDA + (lane >> 4) * 8) * 2;
    const uint32_t boff = (uint32_t)(((grp & 1) * 8 + r8) * HG_LDB + ((grp & 2) ? 8 : 0)) * 2;

    for (int c = 0; c < NC; c++){
        if (c + 1 < NC) cp_wait<1>(); else cp_wait<0>();
        __syncthreads();
        const uint32_t sa = sA + (uint32_t)((c & 1) * 128 * HG_LDA * 2) + aoff;
        const uint32_t sb = sB + (uint32_t)((c & 1) * 64 * HG_LDB * 2) + boff;
        #pragma unroll
        for (int ks = 0; ks < 4; ks++){
            uint32_t a0, a1, a2, a3;
            ldsm_x4(a0, a1, a2, a3, sa + (uint32_t)(ks * 16 * 2));
            #pragma unroll
            for (int nb = 0; nb < 16; nb++){
                uint32_t b0, b1, b2, b3;
                ldsm_x4t(b0, b1, b2, b3, sb + (uint32_t)(ks * 16 * HG_LDB + nb * 16) * 2);
                mma16816(acc[2 * nb],     a0, a1, a2, a3, b0, b1);
                mma16816(acc[2 * nb + 1], a0, a1, a2, a3, b2, b3);
            }
        }
        __syncthreads();
        if (c + 2 < NC) hg_load(A, ldA, Bg, sA, sB, c + 2, c & 1, tid);
    }
}

// ---------------- K2: Q/K/V/gate projections (HMMA) --------------------------
__global__ void __launch_bounds__(256, 1) qkvg_h_k()
{
    extern __shared__ char smem[];
    const int z = blockIdx.y, h = z >> 2, t = z & 3;
    const int m0 = blockIdx.x * 128;
    const int tid = threadIdx.x, lane = tid & 31, warp = tid >> 5;
    const __half* A = g_xnh + (size_t)m0 * D_;
    const __half* W = g_wh + ((size_t)t * H_ + h) * D_ * E_;
    float acc[32][4];
    hgemm_main(A, D_, W, 4, smem, acc);

    const int r0l = warp * 16 + (lane >> 2), r1l = r0l + 8;
    if (t != 2) {
        __half* C = (t == 0 ? g_qh : t == 1 ? g_kh : g_gth) + (size_t)h * M_ * E_;
        #pragma unroll
        for (int nb = 0; nb < 32; nb++){
            int col = nb * 8 + (lane & 3) * 2;
            *(__half2*)&C[(size_t)(m0 + r0l) * E_ + col] = __floats2half2_rn(acc[nb][0], acc[nb][1]);
            *(__half2*)&C[(size_t)(m0 + r1l) * E_ + col] = __floats2half2_rn(acc[nb][2], acc[nb][3]);
        }
    } else {
        // transpose via SMEM staging, then coalesced store to g_vt[h*B+b][e][n]
        __half* st = (__half*)smem;
        #pragma unroll
        for (int nb = 0; nb < 32; nb++){
            int col = nb * 8 + (lane & 3) * 2;
            st[(col    ) * VT_LDT + r0l] = __float2half_rn(acc[nb][0]);
            st[(col + 1) * VT_LDT + r0l] = __float2half_rn(acc[nb][1]);
            st[(col    ) * VT_LDT + r1l] = __float2half_rn(acc[nb][2]);
            st[(col + 1) * VT_LDT + r1l] = __float2half_rn(acc[nb][3]);
        }
        __syncthreads();
        const int bidx = m0 >> 11, n0 = m0 & (N_ - 1);
        __half* dst = g_vt + (size_t)(h * B_ + bidx) * E_ * N_;
        #pragma unroll
        for (int i = 0; i < 16; i++){
            int chunk = tid + i * 256;          // 4096 chunks of 8 halves
            int e = chunk >> 4, off = (chunk & 15) * 8;
            *(uint4*)&dst[(size_t)e * N_ + n0 + off] = *(uint4*)&st[e * VT_LDT + off];
        }
    }
}

// =================== K3: HMMA flash attention =================================
#define LDK 264
#define LDV 72
#define SM_Q   0
#define SM_K   (128 * LDK)
#define SM_V   (SM_K + 2 * 64 * LDK)
#define SMEM_H (SM_V + 2 * 256 * LDV)
#define SMEM_TOT (SMEM_H * 2)              // bytes = 208896

__global__ void __launch_bounds__(256, 1) attn_mma_k(const float* __restrict__ mask)
{
    extern __shared__ __half sm[];
    const int tid = threadIdx.x, lane = tid & 31, warp = tid >> 5;
    const int qt = blockIdx.x, hb = blockIdx.y, bidx = hb & (B_ - 1);
    const int qbase = qt * 128;
    const __half* Qg = g_qh + (size_t)hb * N_ * E_ + (size_t)qbase * E_;
    const __half* Kg = g_kh + (size_t)hb * N_ * E_;
    const __half* Vt = g_vt + (size_t)hb * E_ * N_;
    __half* Og = g_oh + (size_t)hb * N_ * E_;
    const float* mrow = mask + (size_t)bidx * N_;

    const uint32_t sQ = s2u(sm + SM_Q);
    const uint32_t sK = s2u(sm + SM_K);
    const uint32_t sV = s2u(sm + SM_V);

    #pragma unroll
    for (int it = 0; it < 16; it++) {
        int idx = tid + it * 256;
        int row = idx >> 5, c = idx & 31;
        cp16(sQ + (uint32_t)(row * LDK + c * 8) * 2, Qg + (size_t)row * E_ + c * 8);
    }
    #pragma unroll
    for (int buf = 0; buf < 2; buf++) {
        #pragma unroll
        for (int it = 0; it < 8; it++) {
            int idx = tid + it * 256;
            int row = idx >> 5, c = idx & 31;
            cp16(sK + (uint32_t)(buf * 64 * LDK + row * LDK + c * 8) * 2,
                 Kg + (size_t)(buf * 64 + row) * E_ + c * 8);
        }
        #pragma unroll
        for (int it = 0; it < 8; it++) {
            int idx = tid + it * 256;
            int e = idx >> 3, c = idx & 7;
            cp16(sV + (uint32_t)(buf * 256 * LDV + e * LDV + c * 8) * 2,
                 Vt + (size_t)e * N_ + buf * 64 + c * 8);
        }
        cp_commit();
    }

    const int grp = lane >> 3, r8 = lane & 7;
    const int moff = (grp & 2) ? 8 : 0;
    const int koff = (grp & 1) ? 8 : 0;
    const uint32_t qaddr0 = sQ + (uint32_t)((warp * 16 + (lane & 15)) * LDK + (lane >> 4) * 8) * 2;
    const uint32_t kaddr0 = sK + (uint32_t)((moff + r8) * LDK + koff) * 2;
    const uint32_t vaddr0 = sV + (uint32_t)((moff + r8) * LDV + koff) * 2;

    float O[32][4];
    #pragma unroll
    for (int i = 0; i < 32; i++)
        #pragma unroll
        for (int j = 0; j < 4; j++) O[i][j] = 0.f;
    float l0 = 0.f, l1 = 0.f;

    for (int kc = 0; kc < 32; kc++) {
        if (kc == 31) cp_wait<0>(); else cp_wait<1>();
        __syncthreads();
        const int kb = kc * 64;
        const uint32_t kbuf = kaddr0 + (uint32_t)((kc & 1) * 64 * LDK) * 2;
        const uint32_t vbuf = vaddr0 + (uint32_t)((kc & 1) * 256 * LDV) * 2;

        float S[8][4];
        #pragma unroll
        for (int i = 0; i < 8; i++)
            #pragma unroll
            for (int j = 0; j < 4; j++) S[i][j] = 0.f;

        #pragma unroll
        for (int ks = 0; ks < 16; ks++) {
            uint32_t q0, q1, q2, q3;
            ldsm_x4(q0, q1, q2, q3, qaddr0 + (uint32_t)(ks * 32));
            #pragma unroll
            for (int nbp = 0; nbp < 4; nbp++) {
                uint32_t b0, b1, b2, b3;
                ldsm_x4(b0, b1, b2, b3, kbuf + (uint32_t)(nbp * 16 * LDK * 2 + ks * 32));
                mma16816(S[2 * nbp],     q0, q1, q2, q3, b0, b1);
                mma16816(S[2 * nbp + 1], q0, q1, q2, q3, b2, b3);
            }
        }

        uint32_t pa[4][4];
        #pragma unroll
        for (int nb = 0; nb < 8; nb++) {
            int cb = kb + nb * 8 + (lane & 3) * 2;
            float km0 = (__ldg(mrow + cb)     == PADV) ? 0.f : 1.f;
            float km1 = (__ldg(mrow + cb + 1) == PADV) ? 0.f : 1.f;
            float p0 = __expf(S[nb][0] * SCALE_) * km0;
            float p1 = __expf(S[nb][1] * SCALE_) * km1;
            float p2 = __expf(S[nb][2] * SCALE_) * km0;
            float p3 = __expf(S[nb][3] * SCALE_) * km1;
            l0 += p0 + p1;
            l1 += p2 + p3;
            __half2 h01 = __floats2half2_rn(p0, p1);
            __half2 h23 = __floats2half2_rn(p2, p3);
            pa[nb >> 1][(nb & 1) * 2]     = *(uint32_t*)&h01;
            pa[nb >> 1][(nb & 1) * 2 + 1] = *(uint32_t*)&h23;
        }

        #pragma unroll
        for (int ebp = 0; ebp < 16; ebp++) {
            #pragma unroll
            for (int ks = 0; ks < 4; ks++) {
                uint32_t v0, v1, v2, v3;
                ldsm_x4(v0, v1, v2, v3, vbuf + (uint32_t)(ebp * 16 * LDV * 2 + ks * 32));
                mma16816(O[2 * ebp],     pa[ks][0], pa[ks][1], pa[ks][2], pa[ks][3], v0, v1);
                mma16816(O[2 * ebp + 1], pa[ks][0], pa[ks][1], pa[ks][2], pa[ks][3], v2, v3);
            }
        }

        __syncthreads();
        if (kc + 2 < 32) {
            const int nb2 = kb + 128;
            #pragma unroll
            for (int it = 0; it < 8; it++) {
                int idx = tid + it * 256;
                int row = idx >> 5, c = idx & 31;
                cp16(sK + (uint32_t)((kc & 1) * 64 * LDK + row * LDK + c * 8) * 2,
                     Kg + (size_t)(nb2 + row) * E_ + c * 8);
            }
            #pragma unroll
            for (int it = 0; it < 8; it++) {
                int idx = tid + it * 256;
                int e = idx >> 3, c = idx & 7;
                cp16(sV + (uint32_t)((kc & 1) * 256 * LDV + e * LDV + c * 8) * 2,
                     Vt + (size_t)e * N_ + nb2 + c * 8);
            }
            cp_commit();
        }
    }

    l0 += __shfl_xor_sync(0xffffffffu, l0, 1);
    l0 += __shfl_xor_sync(0xffffffffu, l0, 2);
    l1 += __shfl_xor_sync(0xffffffffu, l1, 1);
    l1 += __shfl_xor_sync(0xffffffffu, l1, 2);
    const int r0 = qbase + warp * 16 + (lane >> 2);
    const int r1 = r0 + 8;
    float inv0 = ((mrow[r0] == PADV) ? 0.f : 1.f) / fmaxf(l0, 1e-30f);
    float inv1 = ((mrow[r1] == PADV) ? 0.f : 1.f) / fmaxf(l1, 1e-30f);
    #pragma unroll
    for (int eb = 0; eb < 32; eb++) {
        int col = eb * 8 + (lane & 3) * 2;
        *(__half2*)&Og[(size_t)r0 * E_ + col] = __floats2half2_rn(O[eb][0] * inv0, O[eb][1] * inv0);
        *(__half2*)&Og[(size_t)r1 * E_ + col] = __floats2half2_rn(O[eb][2] * inv1, O[eb][3] * inv1);
    }
}

// ---------------- K4: gate + residual + per-head LN + concat (fp16 io) ------
__global__ void epi_k(const float* __restrict__ x,
                      const float* __restrict__ gr, const float* __restrict__ br)
{
    int m = blockIdx.x, e = threadIdx.x;
    float xv = x[(size_t)m * D_ + e];
    for (int h = 0; h < H_; h++) {
        size_t off = ((size_t)h * M_ + m) * E_ + e;
        float ov = __half2float(g_oh[off]);
        float gv = __half2float(g_gth[off]);
        float sg = 1.f / (1.f + __expf(-gv));
        float t  = ov * sg + xv;
        float mean, var;
        block_meanvar(t, mean, var);
        float yn = (t - mean) * rsqrtf(var + EPS_) * gr[e] + br[e];
        g_yh[(size_t)m * (H_ * E_) + e * H_ + h] = __float2half_rn(yn);
    }
}

// ---------------- K5: output projection (HMMA) + bias + residual ------------
__global__ void __launch_bounds__(256, 1) outproj_h_k(
    const float* __restrict__ out_b, const float* __restrict__ x)
{
    extern __shared__ char smem[];
    const int m0 = blockIdx.x * 128;
    const int tid = threadIdx.x, lane = tid & 31, warp = tid >> 5;
    const __half* A = g_yh + (size_t)m0 * (H_ * E_);
    float acc[32][4];
    hgemm_main(A, H_ * E_, g_w1h, 16, smem, acc);

    const int r0l = warp * 16 + (lane >> 2), r1l = r0l + 8;
    #pragma unroll
    for (int nb = 0; nb < 32; nb++){
        int col = nb * 8 + (lane & 3) * 2;
        float b0 = out_b[col], b1 = out_b[col + 1];
        int m0g = m0 + r0l, m1g = m0 + r1l;
        float2 x0 = *(const float2*)&x[(size_t)m0g * D_ + col];
        float2 x1 = *(const float2*)&x[(size_t)m1g * D_ + col];
        *(float2*)&g_z[(size_t)m0g * E_ + col] = make_float2(acc[nb][0] + b0 + x0.x, acc[nb][1] + b1 + x0.y);
        *(float2*)&g_z[(size_t)m1g * E_ + col] = make_float2(acc[nb][2] + b0 + x1.x, acc[nb][3] + b1 + x1.y);
    }
}

// ---------------- K6: final LN * mask ----------------------------------------
__global__ void final_k(const float* __restrict__ mask,
                        const float* __restrict__ go, const float* __restrict__ bo,
                        float* __restrict__ out)
{
    int m = blockIdx.x, e = threadIdx.x;
    float v = g_z[(size_t)m * E_ + e];
    float mean, var;
    block_meanvar(v, mean, var);
    float mv = (mask[m] == PADV) ? 0.f : 1.f;
    out[(size_t)m * E_ + e] = ((v - mean) * rsqrtf(var + EPS_) * go[e] + bo[e]) * mv;
}

// ---------------- launch ------------------------------------------------------
extern "C" void kernel_launch(void* const* d_in, const int* in_sizes, int n_in,
                              void* d_out, int out_size)
{
    (void)in_sizes; (void)n_in; (void)out_size;
    const float* x     = (const float*)d_in[0];
    const float* mask  = (const float*)d_in[1];
    const float* Wq    = (const float*)d_in[2];
    const float* Wk    = (const float*)d_in[3];
    const float* Wv    = (const float*)d_in[4];
    const float* Wg    = (const float*)d_in[5];
    const float* out_w = (const float*)d_in[6];
    const float* out_b = (const float*)d_in[7];
    const float* g_in  = (const float*)d_in[8];
    const float* b_in  = (const float*)d_in[9];
    const float* g_res = (const float*)d_in[10];
    const float* b_res = (const float*)d_in[11];
    const float* g_out = (const float*)d_in[12];
    const float* b_out = (const float*)d_in[13];
    float* out = (float*)d_out;

    cudaFuncSetAttribute(attn_mma_k,  cudaFuncAttributeMaxDynamicSharedMemorySize, SMEM_TOT);
    cudaFuncSetAttribute(qkvg_h_k,    cudaFuncAttributeMaxDynamicSharedMemorySize, HG_SMEM);
    cudaFuncSetAttribute(outproj_h_k, cudaFuncAttributeMaxDynamicSharedMemorySize, HG_SMEM);

    ln_in_k<<<M_, 256>>>(x, g_in, b_in);

    dim3 gw(D_ * E_ / 1024, 5);                // (256, 5) — note H*D*E/1024 = 256 per tensor... grid.x covers one head-set
    // each tensor has H_*D_*E_ = 262144 elems; threads*4 = 1024 per block -> 256 blocks
    wconv_k<<<dim3(H_ * D_ * E_ / 1024, 5), 256>>>(Wq, Wk, Wv, Wg, out_w);

    dim3 g2(M_ / 128, HB_);                    // (64, 16)
    qkvg_h_k<<<g2, 256, HG_SMEM>>>();

    dim3 g3(N_ / 128, HB_);                    // (16, 16)
    attn_mma_k<<<g3, 256, SMEM_TOT>>>(mask);

    epi_k<<<M_, 256>>>(x, g_res, b_res);

    outproj_h_k<<<M_ / 128, 256, HG_SMEM>>>(out_b, x);

    final_k<<<M_, 256>>>(mask, g_out, b_out, out);
}

// round 5
// speedup vs baseline: 7.9659x; 1.0153x over previous
#include <cuda_runtime.h>
#include <cuda_fp16.h>
#include <math.h>
#include <stdint.h>

#define B_  4
#define N_  2048
#define D_  256
#define H_  4
#define E_  256
#define EV_ (E_+8)           // V^T rows incl. ones row at 256
#define M_  (B_*N_)          // 8192 rows
#define HB_ (H_*B_)          // 16
#define PADV (-2.0f)
#define EPS_ 1e-6f
#define CL2E 0.09016844f     // (1/sqrt(256)) * log2(e)

// ---------------- scratch (device globals; no runtime alloc) ----------------
__device__ __half g_xnh[(size_t)M_*D_];          // LN(x) fp16
__device__ __half g_qh [(size_t)HB_*N_*E_];      // Q fp16 [h][m][e]
__device__ __half g_kh [(size_t)HB_*N_*E_];      // K fp16 [h][m][e]
__device__ __half g_vt [(size_t)HB_*EV_*N_];     // V^T fp16 [h][b][e][n]; row 256 = ones, 257-263 = 0
__device__ __half g_gth[(size_t)HB_*N_*E_];      // gate pre-activation fp16
__device__ __half g_oh [(size_t)HB_*N_*E_];      // attention output fp16
__device__ __half g_yh [(size_t)M_*H_*E_];       // concat fp16 [m][h*E+e] (weights permuted to match)
__device__ float  g_z  [(size_t)M_*E_];          // pre-final-LN fp32
__device__ __half g_wh [(size_t)4*H_*D_*E_];     // qkvg weights fp16 [t][h][d][e]
__device__ __half g_w1h[(size_t)H_*E_*E_];       // out_w fp16, rows permuted to [h*E+e]

// =================== PTX helpers (compute_103-safe) ===================
__device__ __forceinline__ uint32_t s2u(const void* p){
    uint32_t a;
    asm("{ .reg .u64 t; cvta.to.shared.u64 t, %1; cvt.u32.u64 %0, t; }" : "=r"(a) : "l"(p));
    return a;
}
__device__ __forceinline__ void cp16(uint32_t s, const void* g){
    asm volatile("cp.async.cg.shared.global [%0], [%1], 16;" :: "r"(s), "l"(g));
}
__device__ __forceinline__ void cp_commit(){ asm volatile("cp.async.commit_group;" ::: "memory"); }
template<int NN> __device__ __forceinline__ void cp_wait(){
    asm volatile("cp.async.wait_group %0;" :: "n"(NN) : "memory");
}
__device__ __forceinline__ void ldsm_x4(uint32_t& r0, uint32_t& r1, uint32_t& r2, uint32_t& r3, uint32_t addr){
    asm volatile("ldmatrix.sync.aligned.m8n8.x4.shared.b16 {%0,%1,%2,%3}, [%4];"
        : "=r"(r0), "=r"(r1), "=r"(r2), "=r"(r3) : "r"(addr));
}
__device__ __forceinline__ void ldsm_x2(uint32_t& r0, uint32_t& r1, uint32_t addr){
    asm volatile("ldmatrix.sync.aligned.m8n8.x2.shared.b16 {%0,%1}, [%2];"
        : "=r"(r0), "=r"(r1) : "r"(addr));
}
__device__ __forceinline__ void ldsm_x4t(uint32_t& r0, uint32_t& r1, uint32_t& r2, uint32_t& r3, uint32_t addr){
    asm volatile("ldmatrix.sync.aligned.m8n8.x4.trans.shared.b16 {%0,%1,%2,%3}, [%4];"
        : "=r"(r0), "=r"(r1), "=r"(r2), "=r"(r3) : "r"(addr));
}
__device__ __forceinline__ void mma16816(float c[4], uint32_t a0, uint32_t a1, uint32_t a2, uint32_t a3,
                                         uint32_t b0, uint32_t b1){
    asm volatile("mma.sync.aligned.m16n8k16.row.col.f32.f16.f16.f32 "
        "{%0,%1,%2,%3}, {%4,%5,%6,%7}, {%8,%9}, {%0,%1,%2,%3};"
        : "+f"(c[0]), "+f"(c[1]), "+f"(c[2]), "+f"(c[3])
        : "r"(a0), "r"(a1), "r"(a2), "r"(a3), "r"(b0), "r"(b1));
}
__device__ __forceinline__ uint32_t pack2(float hi, float lo){
    uint32_t d; asm("cvt.rn.f16x2.f32 %0, %1, %2;" : "=r"(d) : "f"(hi), "f"(lo)); return d;
}
__device__ __forceinline__ uint32_t ex2h2(uint32_t a){
    uint32_t d; asm("ex2.approx.f16x2 %0, %1;" : "=r"(d) : "r"(a)); return d;
}
__device__ __forceinline__ uint32_t mulh2(uint32_t a, uint32_t b){
    uint32_t d; asm("mul.f16x2 %0, %1, %2;" : "=r"(d) : "r"(a), "r"(b)); return d;
}

// ---------------- warp row-reduction helper ----------------------------------
__device__ __forceinline__ void warp_meanvar(float s, float s2, float& mean, float& var){
    #pragma unroll
    for (int o = 16; o; o >>= 1) {
        s  += __shfl_xor_sync(0xffffffffu, s,  o);
        s2 += __shfl_xor_sync(0xffffffffu, s2, o);
    }
    mean = s * (1.0f / 256.0f);
    var  = s2 * (1.0f / 256.0f) - mean * mean;
}

// ---------------- K1: input LN (warp per row, fp16 out) ----------------------
__global__ void __launch_bounds__(256) ln_in_k(const float* __restrict__ x,
                        const float* __restrict__ g, const float* __restrict__ b) {
    int row = blockIdx.x * 8 + (threadIdx.x >> 5);
    int lane = threadIdx.x & 31;
    const float4* xr = (const float4*)(x + (size_t)row * D_) + lane * 2;
    float4 v0 = xr[0], v1 = xr[1];
    float s  = v0.x + v0.y + v0.z + v0.w + v1.x + v1.y + v1.z + v1.w;
    float s2 = v0.x*v0.x + v0.y*v0.y + v0.z*v0.z + v0.w*v0.w
             + v1.x*v1.x + v1.y*v1.y + v1.z*v1.z + v1.w*v1.w;
    float mean, var; warp_meanvar(s, s2, mean, var);
    float rs = rsqrtf(var + EPS_);
    float4 g0 = ((const float4*)g)[lane*2], g1 = ((const float4*)g)[lane*2+1];
    float4 b0 = ((const float4*)b)[lane*2], b1 = ((const float4*)b)[lane*2+1];
    uint32_t o[4];
    o[0] = pack2((v0.y-mean)*rs*g0.y+b0.y, (v0.x-mean)*rs*g0.x+b0.x);
    o[1] = pack2((v0.w-mean)*rs*g0.w+b0.w, (v0.z-mean)*rs*g0.z+b0.z);
    o[2] = pack2((v1.y-mean)*rs*g1.y+b1.y, (v1.x-mean)*rs*g1.x+b1.x);
    o[3] = pack2((v1.w-mean)*rs*g1.w+b1.w, (v1.z-mean)*rs*g1.z+b1.z);
    *(uint4*)(g_xnh + (size_t)row * D_ + lane * 8) = *(uint4*)o;
}

// ---------------- K1b: weight conversion fp32 -> fp16 (+out_w row permute) --
__global__ void wconv_k(const float* __restrict__ Wq, const float* __restrict__ Wk,
                        const float* __restrict__ Wv, const float* __restrict__ Wg,
                        const float* __restrict__ ow) {
    int t = blockIdx.y;
    const float* src = (t == 0) ? Wq : (t == 1) ? Wk : (t == 2) ? Wv : (t == 3) ? Wg : ow;
    int idx = (blockIdx.x * 256 + threadIdx.x) * 4;
    float4 v = *(const float4*)(src + idx);
    __half2 h0 = __floats2half2_rn(v.x, v.y), h1 = __floats2half2_rn(v.z, v.w);
    if (t < 4) {
        __half2* d2 = (__half2*)(g_wh + (size_t)t * (H_ * D_ * E_) + idx);
        d2[0] = h0; d2[1] = h1;
    } else {
        int rr = idx >> 8, col = idx & 255;       // src row = e*H + h
        int e = rr >> 2, h = rr & 3;
        __half2* d2 = (__half2*)(g_w1h + (size_t)(h * E_ + e) * E_ + col);
        d2[0] = h0; d2[1] = h1;
    }
}

// ---------------- K1c: ones row (e=256) of V^T --------------------------------
__global__ void vones_k() {
    int hb = blockIdx.x;
    __half* dst = g_vt + (size_t)hb * EV_ * N_ + (size_t)E_ * N_ + threadIdx.x * 8;
    __half2 one2 = __floats2half2_rn(1.f, 1.f);
    uint32_t u = *(uint32_t*)&one2;
    uint4 v = make_uint4(u, u, u, u);
    *(uint4*)dst = v;
}

// =================== HMMA GEMM mainloop: 128 x 256 tile =======================
#define HG_LDA 72
#define HG_LDB 264
#define HG_BS_OFF 36864
#define HG_SMEM 104448
#define VT_LDT 136

__device__ __forceinline__ void hg_load(const __half* A, int ldA, const __half* Bg,
                                        uint32_t sA, uint32_t sB, int c, int buf, int tid){
    #pragma unroll
    for (int it = 0; it < 4; it++){
        int idx = tid + it * 256;
        int row = idx >> 3, cg = idx & 7;
        cp16(sA + (uint32_t)(buf * 128 * HG_LDA + row * HG_LDA + cg * 8) * 2,
             A + (size_t)row * ldA + c * 64 + cg * 8);
    }
    #pragma unroll
    for (int it = 0; it < 8; it++){
        int idx = tid + it * 256;
        int row = idx >> 5, cg = idx & 31;
        cp16(sB + (uint32_t)(buf * 64 * HG_LDB + row * HG_LDB + cg * 8) * 2,
             Bg + (size_t)(c * 64 + row) * 256 + cg * 8);
    }
    cp_commit();
}

__device__ __forceinline__ void hgemm_main(const __half* A, int ldA, const __half* Bg,
                                           int NC, char* smem, float acc[32][4]){
    const int tid = threadIdx.x, lane = tid & 31, warp = tid >> 5;
    const uint32_t sA = s2u(smem), sB = s2u(smem + HG_BS_OFF);
    #pragma unroll
    for (int i = 0; i < 32; i++)
        #pragma unroll
        for (int j = 0; j < 4; j++) acc[i][j] = 0.f;

    hg_load(A, ldA, Bg, sA, sB, 0, 0, tid);
    hg_load(A, ldA, Bg, sA, sB, 1, 1, tid);

    const int grp = lane >> 3, r8 = lane & 7;
    const uint32_t aoff = (uint32_t)((warp * 16 + (lane & 15)) * HG_LDA + (lane >> 4) * 8) * 2;
    const uint32_t boff = (uint32_t)(((grp & 1) * 8 + r8) * HG_LDB + ((grp & 2) ? 8 : 0)) * 2;

    for (int c = 0; c < NC; c++){
        if (c + 1 < NC) cp_wait<1>(); else cp_wait<0>();
        __syncthreads();
        const uint32_t sa = sA + (uint32_t)((c & 1) * 128 * HG_LDA * 2) + aoff;
        const uint32_t sb = sB + (uint32_t)((c & 1) * 64 * HG_LDB * 2) + boff;
        #pragma unroll
        for (int ks = 0; ks < 4; ks++){
            uint32_t a0, a1, a2, a3;
            ldsm_x4(a0, a1, a2, a3, sa + (uint32_t)(ks * 16 * 2));
            #pragma unroll
            for (int nb = 0; nb < 16; nb++){
                uint32_t b0, b1, b2, b3;
                ldsm_x4t(b0, b1, b2, b3, sb + (uint32_t)(ks * 16 * HG_LDB + nb * 16) * 2);
                mma16816(acc[2 * nb],     a0, a1, a2, a3, b0, b1);
                mma16816(acc[2 * nb + 1], a0, a1, a2, a3, b2, b3);
            }
        }
        __syncthreads();
        if (c + 2 < NC) hg_load(A, ldA, Bg, sA, sB, c + 2, c & 1, tid);
    }
}

// ---------------- K2: Q/K/V/gate projections (HMMA) --------------------------
__global__ void __launch_bounds__(256, 1) qkvg_h_k()
{
    extern __shared__ char smem[];
    const int z = blockIdx.y, h = z >> 2, t = z & 3;
    const int m0 = blockIdx.x * 128;
    const int tid = threadIdx.x, lane = tid & 31, warp = tid >> 5;
    const __half* A = g_xnh + (size_t)m0 * D_;
    const __half* W = g_wh + ((size_t)t * H_ + h) * D_ * E_;
    float acc[32][4];
    hgemm_main(A, D_, W, 4, smem, acc);

    const int r0l = warp * 16 + (lane >> 2), r1l = r0l + 8;
    if (t != 2) {
        __half* C = (t == 0 ? g_qh : t == 1 ? g_kh : g_gth) + (size_t)h * M_ * E_;
        #pragma unroll
        for (int nb = 0; nb < 32; nb++){
            int col = nb * 8 + (lane & 3) * 2;
            *(__half2*)&C[(size_t)(m0 + r0l) * E_ + col] = __floats2half2_rn(acc[nb][0], acc[nb][1]);
            *(__half2*)&C[(size_t)(m0 + r1l) * E_ + col] = __floats2half2_rn(acc[nb][2], acc[nb][3]);
        }
    } else {
        __half* st = (__half*)smem;
        #pragma unroll
        for (int nb = 0; nb < 32; nb++){
            int col = nb * 8 + (lane & 3) * 2;
            st[(col    ) * VT_LDT + r0l] = __float2half_rn(acc[nb][0]);
            st[(col + 1) * VT_LDT + r0l] = __float2half_rn(acc[nb][1]);
            st[(col    ) * VT_LDT + r1l] = __float2half_rn(acc[nb][2]);
            st[(col + 1) * VT_LDT + r1l] = __float2half_rn(acc[nb][3]);
        }
        __syncthreads();
        const int bidx = m0 >> 11, n0 = m0 & (N_ - 1);
        __half* dst = g_vt + (size_t)(h * B_ + bidx) * EV_ * N_;
        #pragma unroll
        for (int i = 0; i < 16; i++){
            int chunk = tid + i * 256;
            int e = chunk >> 4, off = (chunk & 15) * 8;
            *(uint4*)&dst[(size_t)e * N_ + n0 + off] = *(uint4*)&st[e * VT_LDT + off];
        }
    }
}

// =================== K3: HMMA flash attention =================================
#define LDK 264
#define LDV 72
#define SM_Q   0
#define SM_K   (128 * LDK)
#define SM_V   (SM_K + 2 * 64 * LDK)
#define SM_KM  (SM_V + 2 * 264 * LDV)
#define SMEM_H (SM_KM + 64)
#define SMEM_TOT (SMEM_H * 2)              // 211456 bytes

__global__ void __launch_bounds__(256, 1) attn_mma_k(const float* __restrict__ mask)
{
    extern __shared__ __half sm[];
    const int tid = threadIdx.x, lane = tid & 31, warp = tid >> 5;
    const int qt = blockIdx.x, hb = blockIdx.y, bidx = hb & (B_ - 1);
    const int qbase = qt * 128;
    const __half* Qg = g_qh + (size_t)hb * N_ * E_ + (size_t)qbase * E_;
    const __half* Kg = g_kh + (size_t)hb * N_ * E_;
    const __half* Vt = g_vt + (size_t)hb * EV_ * N_;
    __half* Og = g_oh + (size_t)hb * N_ * E_;
    const float* mrow = mask + (size_t)bidx * N_;

    const uint32_t sQ = s2u(sm + SM_Q);
    const uint32_t sK = s2u(sm + SM_K);
    const uint32_t sV = s2u(sm + SM_V);
    uint32_t* kmarr = (uint32_t*)(sm + SM_KM);

    #pragma unroll
    for (int it = 0; it < 16; it++) {
        int idx = tid + it * 256;
        int row = idx >> 5, c = idx & 31;
        cp16(sQ + (uint32_t)(row * LDK + c * 8) * 2, Qg + (size_t)row * E_ + c * 8);
    }
    #pragma unroll
    for (int buf = 0; buf < 2; buf++) {
        #pragma unroll
        for (int it = 0; it < 8; it++) {
            int idx = tid + it * 256;
            int row = idx >> 5, c = idx & 31;
            cp16(sK + (uint32_t)(buf * 64 * LDK + row * LDK + c * 8) * 2,
                 Kg + (size_t)(buf * 64 + row) * E_ + c * 8);
        }
        #pragma unroll
        for (int it = 0; it < 9; it++) {
            int idx = tid + it * 256;
            if (idx < 264 * 8) {
                int e = idx >> 3, c = idx & 7;
                cp16(sV + (uint32_t)(buf * 264 * LDV + e * LDV + c * 8) * 2,
                     Vt + (size_t)e * N_ + buf * 64 + c * 8);
            }
        }
        cp_commit();
    }

    const int grp = lane >> 3, r8 = lane & 7;
    const int moff = (grp & 2) ? 8 : 0;
    const int koff = (grp & 1) ? 8 : 0;
    const uint32_t qaddr0 = sQ + (uint32_t)((warp * 16 + (lane & 15)) * LDK + (lane >> 4) * 8) * 2;
    const uint32_t kaddr0 = sK + (uint32_t)((moff + r8) * LDK + koff) * 2;
    const uint32_t vaddr0 = sV + (uint32_t)((moff + r8) * LDV + koff) * 2;
    const uint32_t exaddr0 = sV + (uint32_t)((256 + (lane & 7)) * LDV + ((lane >> 3) & 1) * 8) * 2;

    float O[32][4];
    #pragma unroll
    for (int i = 0; i < 32; i++)
        #pragma unroll
        for (int j = 0; j < 4; j++) O[i][j] = 0.f;
    float Oex[4] = {0.f, 0.f, 0.f, 0.f};      // col 256 = row-sum l

    for (int kc = 0; kc < 32; kc++) {
        if (kc == 31) cp_wait<0>(); else cp_wait<1>();
        const int kb = kc * 64;
        if (tid < 32) {
            float a = mrow[kb + tid * 2], b = mrow[kb + tid * 2 + 1];
            __half2 km = __floats2half2_rn((a == PADV) ? 0.f : 1.f, (b == PADV) ? 0.f : 1.f);
            kmarr[tid] = *(uint32_t*)&km;
        }
        __syncthreads();
        const uint32_t kbuf = kaddr0 + (uint32_t)((kc & 1) * 64 * LDK) * 2;
        const uint32_t vbuf = vaddr0 + (uint32_t)((kc & 1) * 264 * LDV) * 2;
        const uint32_t exbuf = exaddr0 + (uint32_t)((kc & 1) * 264 * LDV) * 2;

        float S[8][4];
        #pragma unroll
        for (int i = 0; i < 8; i++)
            #pragma unroll
            for (int j = 0; j < 4; j++) S[i][j] = 0.f;

        #pragma unroll
        for (int ks = 0; ks < 16; ks++) {
            uint32_t q0, q1, q2, q3;
            ldsm_x4(q0, q1, q2, q3, qaddr0 + (uint32_t)(ks * 32));
            #pragma unroll
            for (int nbp = 0; nbp < 4; nbp++) {
                uint32_t b0, b1, b2, b3;
                ldsm_x4(b0, b1, b2, b3, kbuf + (uint32_t)(nbp * 16 * LDK * 2 + ks * 32));
                mma16816(S[2 * nbp],     q0, q1, q2, q3, b0, b1);
                mma16816(S[2 * nbp + 1], q0, q1, q2, q3, b2, b3);
            }
        }

        // ---- softmax: P = ex2(S*scale*log2e) * keymask  (fp16x2 path) ----
        uint32_t pa[4][4];
        #pragma unroll
        for (int nb = 0; nb < 8; nb++) {
            uint32_t km = kmarr[nb * 4 + (lane & 3)];
            uint32_t h01 = pack2(S[nb][1] * CL2E, S[nb][0] * CL2E);
            uint32_t h23 = pack2(S[nb][3] * CL2E, S[nb][2] * CL2E);
            pa[nb >> 1][(nb & 1) * 2]     = mulh2(ex2h2(h01), km);
            pa[nb >> 1][(nb & 1) * 2 + 1] = mulh2(ex2h2(h23), km);
        }

        // ---- O += P V (incl. ones-column for l) ----
        #pragma unroll
        for (int ebp = 0; ebp < 16; ebp++) {
            #pragma unroll
            for (int ks = 0; ks < 4; ks++) {
                uint32_t v0, v1, v2, v3;
                ldsm_x4(v0, v1, v2, v3, vbuf + (uint32_t)(ebp * 16 * LDV * 2 + ks * 32));
                mma16816(O[2 * ebp],     pa[ks][0], pa[ks][1], pa[ks][2], pa[ks][3], v0, v1);
                mma16816(O[2 * ebp + 1], pa[ks][0], pa[ks][1], pa[ks][2], pa[ks][3], v2, v3);
            }
        }
        #pragma unroll
        for (int ks = 0; ks < 4; ks++) {
            uint32_t b0, b1;
            ldsm_x2(b0, b1, exbuf + (uint32_t)(ks * 32));
            mma16816(Oex, pa[ks][0], pa[ks][1], pa[ks][2], pa[ks][3], b0, b1);
        }

        __syncthreads();
        if (kc + 2 < 32) {
            const int nb2 = kb + 128;
            #pragma unroll
            for (int it = 0; it < 8; it++) {
                int idx = tid + it * 256;
                int row = idx >> 5, c = idx & 31;
                cp16(sK + (uint32_t)((kc & 1) * 64 * LDK + row * LDK + c * 8) * 2,
                     Kg + (size_t)(nb2 + row) * E_ + c * 8);
            }
            #pragma unroll
            for (int it = 0; it < 9; it++) {
                int idx = tid + it * 256;
                if (idx < 264 * 8) {
                    int e = idx >> 3, c = idx & 7;
                    cp16(sV + (uint32_t)((kc & 1) * 264 * LDV + e * LDV + c * 8) * 2,
                         Vt + (size_t)e * N_ + nb2 + c * 8);
                }
            }
            cp_commit();
        }
    }

    // ---- finalize: l from ones-column (quad-broadcast), normalize, write ----
    float l0 = __shfl_sync(0xffffffffu, Oex[0], lane & ~3);
    float l1 = __shfl_sync(0xffffffffu, Oex[2], lane & ~3);
    const int r0 = qbase + warp * 16 + (lane >> 2);
    const int r1 = r0 + 8;
    float inv0 = ((mrow[r0] == PADV) ? 0.f : 1.f) / fmaxf(l0, 1e-30f);
    float inv1 = ((mrow[r1] == PADV) ? 0.f : 1.f) / fmaxf(l1, 1e-30f);
    #pragma unroll
    for (int eb = 0; eb < 32; eb++) {
        int col = eb * 8 + (lane & 3) * 2;
        *(__half2*)&Og[(size_t)r0 * E_ + col] = __floats2half2_rn(O[eb][0] * inv0, O[eb][1] * inv0);
        *(__half2*)&Og[(size_t)r1 * E_ + col] = __floats2half2_rn(O[eb][2] * inv1, O[eb][3] * inv1);
    }
}

// ---------------- K4: gate + residual + per-head LN + concat (warp/row) -----
__global__ void __launch_bounds__(256) epi_k(const float* __restrict__ x,
                      const float* __restrict__ gr, const float* __restrict__ br)
{
    int row = blockIdx.x * 8 + (threadIdx.x >> 5);   // row = m*4 + h
    int lane = threadIdx.x & 31;
    int m = row >> 2, h = row & 3;
    size_t off = ((size_t)h * M_ + m) * E_ + lane * 8;
    uint4 ou = *(uint4*)(g_oh + off);
    uint4 gu = *(uint4*)(g_gth + off);
    const float4* xr = (const float4*)(x + (size_t)m * D_) + lane * 2;
    float4 x0 = xr[0], x1 = xr[1];
    float xv[8] = {x0.x, x0.y, x0.z, x0.w, x1.x, x1.y, x1.z, x1.w};
    float t[8];
    const uint32_t* op = (const uint32_t*)&ou;
    const uint32_t* gp = (const uint32_t*)&gu;
    float s = 0.f, s2 = 0.f;
    #pragma unroll
    for (int j = 0; j < 4; j++) {
        float2 o2 = __half22float2(*(const __half2*)&op[j]);
        float2 g2 = __half22float2(*(const __half2*)&gp[j]);
        float sg0 = 1.f / (1.f + __expf(-g2.x));
        float sg1 = 1.f / (1.f + __expf(-g2.y));
        t[2*j]   = o2.x * sg0 + xv[2*j];
        t[2*j+1] = o2.y * sg1 + xv[2*j+1];
        s += t[2*j] + t[2*j+1];
        s2 += t[2*j]*t[2*j] + t[2*j+1]*t[2*j+1];
    }
    float mean, var; warp_meanvar(s, s2, mean, var);
    float rs = rsqrtf(var + EPS_);
    float4 gr0 = ((const float4*)gr)[lane*2], gr1 = ((const float4*)gr)[lane*2+1];
    float4 br0 = ((const float4*)br)[lane*2], br1 = ((const float4*)br)[lane*2+1];
    float grv[8] = {gr0.x, gr0.y, gr0.z, gr0.w, gr1.x, gr1.y, gr1.z, gr1.w};
    float brv[8] = {br0.x, br0.y, br0.z, br0.w, br1.x, br1.y, br1.z, br1.w};
    uint32_t out[4];
    #pragma unroll
    for (int j = 0; j < 4; j++)
        out[j] = pack2((t[2*j+1]-mean)*rs*grv[2*j+1]+brv[2*j+1],
                       (t[2*j]  -mean)*rs*grv[2*j]  +brv[2*j]);
    *(uint4*)(g_yh + (size_t)m * (H_ * E_) + h * E_ + lane * 8) = *(uint4*)out;
}

// ---------------- K5: output projection (HMMA) + bias + residual ------------
__global__ void __launch_bounds__(256, 1) outproj_h_k(
    const float* __restrict__ out_b, const float* __restrict__ x)
{
    extern __shared__ char smem[];
    const int m0 = blockIdx.x * 128;
    const int tid = threadIdx.x, lane = tid & 31, warp = tid >> 5;
    const __half* A = g_yh + (size_t)m0 * (H_ * E_);
    float acc[32][4];
    hgemm_main(A, H_ * E_, g_w1h, 16, smem, acc);

    const int r0l = warp * 16 + (lane >> 2), r1l = r0l + 8;
    #pragma unroll
    for (int nb = 0; nb < 32; nb++){
        int col = nb * 8 + (lane & 3) * 2;
        float b0 = out_b[col], b1 = out_b[col + 1];
        int m0g = m0 + r0l, m1g = m0 + r1l;
        float2 x0 = *(const float2*)&x[(size_t)m0g * D_ + col];
        float2 x1 = *(const float2*)&x[(size_t)m1g * D_ + col];
        *(float2*)&g_z[(size_t)m0g * E_ + col] = make_float2(acc[nb][0] + b0 + x0.x, acc[nb][1] + b1 + x0.y);
        *(float2*)&g_z[(size_t)m1g * E_ + col] = make_float2(acc[nb][2] + b0 + x1.x, acc[nb][3] + b1 + x1.y);
    }
}

// ---------------- K6: final LN * mask (warp per row) -------------------------
__global__ void __launch_bounds__(256) final_k(const float* __restrict__ mask,
                        const float* __restrict__ go, const float* __restrict__ bo,
                        float* __restrict__ out)
{
    int row = blockIdx.x * 8 + (threadIdx.x >> 5);
    int lane = threadIdx.x & 31;
    const float4* zr = (const float4*)(g_z + (size_t)row * E_) + lane * 2;
    float4 v0 = zr[0], v1 = zr[1];
    float s  = v0.x + v0.y + v0.z + v0.w + v1.x + v1.y + v1.z + v1.w;
    float s2 = v0.x*v0.x + v0.y*v0.y + v0.z*v0.z + v0.w*v0.w
             + v1.x*v1.x + v1.y*v1.y + v1.z*v1.z + v1.w*v1.w;
    float mean, var; warp_meanvar(s, s2, mean, var);
    float rs = rsqrtf(var + EPS_);
    float mv = (mask[row] == PADV) ? 0.f : 1.f;
    float4 g0 = ((const float4*)go)[lane*2], g1 = ((const float4*)go)[lane*2+1];
    float4 b0 = ((const float4*)bo)[lane*2], b1 = ((const float4*)bo)[lane*2+1];
    float4 r0, r1;
    r0.x = ((v0.x-mean)*rs*g0.x+b0.x)*mv; r0.y = ((v0.y-mean)*rs*g0.y+b0.y)*mv;
    r0.z = ((v0.z-mean)*rs*g0.z+b0.z)*mv; r0.w = ((v0.w-mean)*rs*g0.w+b0.w)*mv;
    r1.x = ((v1.x-mean)*rs*g1.x+b1.x)*mv; r1.y = ((v1.y-mean)*rs*g1.y+b1.y)*mv;
    r1.z = ((v1.z-mean)*rs*g1.z+b1.z)*mv; r1.w = ((v1.w-mean)*rs*g1.w+b1.w)*mv;
    float4* orow = (float4*)(out + (size_t)row * E_) + lane * 2;
    orow[0] = r0; orow[1] = r1;
}

// ---------------- launch ------------------------------------------------------
extern "C" void kernel_launch(void* const* d_in, const int* in_sizes, int n_in,
                              void* d_out, int out_size)
{
    (void)in_sizes; (void)n_in; (void)out_size;
    const float* x     = (const float*)d_in[0];
    const float* mask  = (const float*)d_in[1];
    const float* Wq    = (const float*)d_in[2];
    const float* Wk    = (const float*)d_in[3];
    const float* Wv    = (const float*)d_in[4];
    const float* Wg    = (const float*)d_in[5];
    const float* out_w = (const float*)d_in[6];
    const float* out_b = (const float*)d_in[7];
    const float* g_in  = (const float*)d_in[8];
    const float* b_in  = (const float*)d_in[9];
    const float* g_res = (const float*)d_in[10];
    const float* b_res = (const float*)d_in[11];
    const float* g_out = (const float*)d_in[12];
    const float* b_out = (const float*)d_in[13];
    float* out = (float*)d_out;

    cudaFuncSetAttribute(attn_mma_k,  cudaFuncAttributeMaxDynamicSharedMemorySize, SMEM_TOT);
    cudaFuncSetAttribute(qkvg_h_k,    cudaFuncAttributeMaxDynamicSharedMemorySize, HG_SMEM);
    cudaFuncSetAttribute(outproj_h_k, cudaFuncAttributeMaxDynamicSharedMemorySize, HG_SMEM);

    ln_in_k<<<M_ / 8, 256>>>(x, g_in, b_in);
    wconv_k<<<dim3(H_ * D_ * E_ / 1024, 5), 256>>>(Wq, Wk, Wv, Wg, out_w);
    vones_k<<<HB_, 256>>>();

    dim3 g2(M_ / 128, HB_);                    // (64, 16)
    qkvg_h_k<<<g2, 256, HG_SMEM>>>();

    dim3 g3(N_ / 128, HB_);                    // (16, 16)
    attn_mma_k<<<g3, 256, SMEM_TOT>>>(mask);

    epi_k<<<M_ * H_ / 8, 256>>>(x, g_res, b_res);

    outproj_h_k<<<M_ / 128, 256, HG_SMEM>>>(out_b, x);

    final_k<<<M_ / 8, 256>>>(mask, g_out, b_out, out);
}

// round 6
// speedup vs baseline: 8.5740x; 1.0763x over previous
#include <cuda_runtime.h>
#include <cuda_fp16.h>
#include <math.h>
#include <stdint.h>

#define B_  4
#define N_  2048
#define D_  256
#define H_  4
#define E_  256
#define M_  (B_*N_)          // 8192 rows
#define HB_ (H_*B_)          // 16
#define PADV (-2.0f)
#define EPS_ 1e-6f
#define CL2E 0.09016844f     // (1/sqrt(256)) * log2(e)

// ---------------- scratch (device globals; no runtime alloc) ----------------
__device__ __half g_xnh[(size_t)M_*D_];          // LN(x) fp16
__device__ __half g_qh [(size_t)HB_*N_*E_];      // Q fp16 [h][m][e]
__device__ __half g_kh [(size_t)HB_*N_*E_];      // K fp16 [h][m][e]
__device__ __half g_vt [(size_t)HB_*E_*N_];      // V^T fp16 [h][b][e][n]
__device__ __half g_gth[(size_t)HB_*N_*E_];      // gate pre-activation fp16
__device__ __half g_oh [(size_t)HB_*N_*E_];      // attention output fp16
__device__ __half g_yh [(size_t)M_*H_*E_];       // concat fp16 [m][h*E+e]
__device__ float  g_z  [(size_t)M_*E_];          // pre-final-LN fp32
__device__ __half g_wh [(size_t)4*H_*D_*E_];     // qkvg weights fp16 [t][h][d][e]
__device__ __half g_w1h[(size_t)H_*E_*E_];       // out_w fp16, rows permuted to [h*E+e]

// =================== PTX helpers (compute_103-safe) ===================
__device__ __forceinline__ uint32_t s2u(const void* p){
    uint32_t a;
    asm("{ .reg .u64 t; cvta.to.shared.u64 t, %1; cvt.u32.u64 %0, t; }" : "=r"(a) : "l"(p));
    return a;
}
__device__ __forceinline__ void cp16(uint32_t s, const void* g){
    asm volatile("cp.async.cg.shared.global [%0], [%1], 16;" :: "r"(s), "l"(g));
}
__device__ __forceinline__ void cp_commit(){ asm volatile("cp.async.commit_group;" ::: "memory"); }
template<int NN> __device__ __forceinline__ void cp_wait(){
    asm volatile("cp.async.wait_group %0;" :: "n"(NN) : "memory");
}
__device__ __forceinline__ void ldsm_x4(uint32_t& r0, uint32_t& r1, uint32_t& r2, uint32_t& r3, uint32_t addr){
    asm volatile("ldmatrix.sync.aligned.m8n8.x4.shared.b16 {%0,%1,%2,%3}, [%4];"
        : "=r"(r0), "=r"(r1), "=r"(r2), "=r"(r3) : "r"(addr));
}
__device__ __forceinline__ void ldsm_x2(uint32_t& r0, uint32_t& r1, uint32_t addr){
    asm volatile("ldmatrix.sync.aligned.m8n8.x2.shared.b16 {%0,%1}, [%2];"
        : "=r"(r0), "=r"(r1) : "r"(addr));
}
__device__ __forceinline__ void ldsm_x4t(uint32_t& r0, uint32_t& r1, uint32_t& r2, uint32_t& r3, uint32_t addr){
    asm volatile("ldmatrix.sync.aligned.m8n8.x4.trans.shared.b16 {%0,%1,%2,%3}, [%4];"
        : "=r"(r0), "=r"(r1), "=r"(r2), "=r"(r3) : "r"(addr));
}
__device__ __forceinline__ void mma16816(float c[4], uint32_t a0, uint32_t a1, uint32_t a2, uint32_t a3,
                                         uint32_t b0, uint32_t b1){
    asm volatile("mma.sync.aligned.m16n8k16.row.col.f32.f16.f16.f32 "
        "{%0,%1,%2,%3}, {%4,%5,%6,%7}, {%8,%9}, {%0,%1,%2,%3};"
        : "+f"(c[0]), "+f"(c[1]), "+f"(c[2]), "+f"(c[3])
        : "r"(a0), "r"(a1), "r"(a2), "r"(a3), "r"(b0), "r"(b1));
}
__device__ __forceinline__ uint32_t pack2(float hi, float lo){
    uint32_t d; asm("cvt.rn.f16x2.f32 %0, %1, %2;" : "=r"(d) : "f"(hi), "f"(lo)); return d;
}
__device__ __forceinline__ uint32_t ex2h2(uint32_t a){
    uint32_t d; asm("ex2.approx.f16x2 %0, %1;" : "=r"(d) : "r"(a)); return d;
}
__device__ __forceinline__ uint32_t mulh2(uint32_t a, uint32_t b){
    uint32_t d; asm("mul.f16x2 %0, %1, %2;" : "=r"(d) : "r"(a), "r"(b)); return d;
}

// ---------------- warp row-reduction helper ----------------------------------
__device__ __forceinline__ void warp_meanvar(float s, float s2, float& mean, float& var){
    #pragma unroll
    for (int o = 16; o; o >>= 1) {
        s  += __shfl_xor_sync(0xffffffffu, s,  o);
        s2 += __shfl_xor_sync(0xffffffffu, s2, o);
    }
    mean = s * (1.0f / 256.0f);
    var  = s2 * (1.0f / 256.0f) - mean * mean;
}

// ---------------- K1: input LN (warp per row, fp16 out) ----------------------
__global__ void __launch_bounds__(256) ln_in_k(const float* __restrict__ x,
                        const float* __restrict__ g, const float* __restrict__ b) {
    int row = blockIdx.x * 8 + (threadIdx.x >> 5);
    int lane = threadIdx.x & 31;
    const float4* xr = (const float4*)(x + (size_t)row * D_) + lane * 2;
    float4 v0 = xr[0], v1 = xr[1];
    float s  = v0.x + v0.y + v0.z + v0.w + v1.x + v1.y + v1.z + v1.w;
    float s2 = v0.x*v0.x + v0.y*v0.y + v0.z*v0.z + v0.w*v0.w
             + v1.x*v1.x + v1.y*v1.y + v1.z*v1.z + v1.w*v1.w;
    float mean, var; warp_meanvar(s, s2, mean, var);
    float rs = rsqrtf(var + EPS_);
    float4 g0 = ((const float4*)g)[lane*2], g1 = ((const float4*)g)[lane*2+1];
    float4 b0 = ((const float4*)b)[lane*2], b1 = ((const float4*)b)[lane*2+1];
    uint32_t o[4];
    o[0] = pack2((v0.y-mean)*rs*g0.y+b0.y, (v0.x-mean)*rs*g0.x+b0.x);
    o[1] = pack2((v0.w-mean)*rs*g0.w+b0.w, (v0.z-mean)*rs*g0.z+b0.z);
    o[2] = pack2((v1.y-mean)*rs*g1.y+b1.y, (v1.x-mean)*rs*g1.x+b1.x);
    o[3] = pack2((v1.w-mean)*rs*g1.w+b1.w, (v1.z-mean)*rs*g1.z+b1.z);
    *(uint4*)(g_xnh + (size_t)row * D_ + lane * 8) = *(uint4*)o;
}

// ---------------- K1b: weight conversion fp32 -> fp16 (+out_w row permute) --
__global__ void wconv_k(const float* __restrict__ Wq, const float* __restrict__ Wk,
                        const float* __restrict__ Wv, const float* __restrict__ Wg,
                        const float* __restrict__ ow) {
    int t = blockIdx.y;
    const float* src = (t == 0) ? Wq : (t == 1) ? Wk : (t == 2) ? Wv : (t == 3) ? Wg : ow;
    int idx = (blockIdx.x * 256 + threadIdx.x) * 4;
    float4 v = *(const float4*)(src + idx);
    __half2 h0 = __floats2half2_rn(v.x, v.y), h1 = __floats2half2_rn(v.z, v.w);
    if (t < 4) {
        __half2* d2 = (__half2*)(g_wh + (size_t)t * (H_ * D_ * E_) + idx);
        d2[0] = h0; d2[1] = h1;
    } else {
        int rr = idx >> 8, col = idx & 255;       // src row = e*H + h
        int e = rr >> 2, h = rr & 3;
        __half2* d2 = (__half2*)(g_w1h + (size_t)(h * E_ + e) * E_ + col);
        d2[0] = h0; d2[1] = h1;
    }
}

// =================== HMMA GEMM mainloop: 128 x 256 tile, m32n128/warp ========
#define HG_LDA 72
#define HG_LDB 264
#define HG_BS_OFF 36864
#define HG_SMEM 104448
#define VT_LDT 136

__device__ __forceinline__ void hg_load(const __half* A, int ldA, const __half* Bg,
                                        uint32_t sA, uint32_t sB, int c, int buf, int tid){
    #pragma unroll
    for (int it = 0; it < 4; it++){
        int idx = tid + it * 256;
        int row = idx >> 3, cg = idx & 7;
        cp16(sA + (uint32_t)(buf * 128 * HG_LDA + row * HG_LDA + cg * 8) * 2,
             A + (size_t)row * ldA + c * 64 + cg * 8);
    }
    #pragma unroll
    for (int it = 0; it < 8; it++){
        int idx = tid + it * 256;
        int row = idx >> 5, cg = idx & 31;
        cp16(sB + (uint32_t)(buf * 64 * HG_LDB + row * HG_LDB + cg * 8) * 2,
             Bg + (size_t)(c * 64 + row) * 256 + cg * 8);
    }
    cp_commit();
}

__device__ __forceinline__ void hgemm_main(const __half* A, int ldA, const __half* Bg,
                                           int NC, char* smem, float acc[2][16][4]){
    const int tid = threadIdx.x, lane = tid & 31, warp = tid >> 5;
    const int wm = warp & 3, wn = warp >> 2;
    const uint32_t sA = s2u(smem), sB = s2u(smem + HG_BS_OFF);
    #pragma unroll
    for (int mi = 0; mi < 2; mi++)
        #pragma unroll
        for (int i = 0; i < 16; i++)
            #pragma unroll
            for (int j = 0; j < 4; j++) acc[mi][i][j] = 0.f;

    hg_load(A, ldA, Bg, sA, sB, 0, 0, tid);
    hg_load(A, ldA, Bg, sA, sB, 1, 1, tid);

    const int grp = lane >> 3, r8 = lane & 7;
    uint32_t aoff[2];
    #pragma unroll
    for (int mi = 0; mi < 2; mi++)
        aoff[mi] = (uint32_t)((wm * 32 + mi * 16 + (lane & 15)) * HG_LDA + (lane >> 4) * 8) * 2;
    const uint32_t boff = (uint32_t)(((grp & 1) * 8 + r8) * HG_LDB + wn * 128 + ((grp & 2) ? 8 : 0)) * 2;

    for (int c = 0; c < NC; c++){
        if (c + 1 < NC) cp_wait<1>(); else cp_wait<0>();
        __syncthreads();
        const uint32_t sa = sA + (uint32_t)((c & 1) * 128 * HG_LDA * 2);
        const uint32_t sb = sB + (uint32_t)((c & 1) * 64 * HG_LDB * 2) + boff;
        #pragma unroll
        for (int ks = 0; ks < 4; ks++){
            uint32_t a[2][4];
            #pragma unroll
            for (int mi = 0; mi < 2; mi++)
                ldsm_x4(a[mi][0], a[mi][1], a[mi][2], a[mi][3], sa + aoff[mi] + (uint32_t)(ks * 32));
            #pragma unroll
            for (int nb = 0; nb < 8; nb++){
                uint32_t b0, b1, b2, b3;
                ldsm_x4t(b0, b1, b2, b3, sb + (uint32_t)(ks * 16 * HG_LDB + nb * 16) * 2);
                #pragma unroll
                for (int mi = 0; mi < 2; mi++){
                    mma16816(acc[mi][2 * nb],     a[mi][0], a[mi][1], a[mi][2], a[mi][3], b0, b1);
                    mma16816(acc[mi][2 * nb + 1], a[mi][0], a[mi][1], a[mi][2], a[mi][3], b2, b3);
                }
            }
        }
        __syncthreads();
        if (c + 2 < NC) hg_load(A, ldA, Bg, sA, sB, c + 2, c & 1, tid);
    }
}

// ---------------- K2: Q/K/V/gate projections (HMMA) --------------------------
__global__ void __launch_bounds__(256, 1) qkvg_h_k()
{
    extern __shared__ char smem[];
    const int z = blockIdx.y, h = z >> 2, t = z & 3;
    const int m0 = blockIdx.x * 128;
    const int tid = threadIdx.x, lane = tid & 31, warp = tid >> 5;
    const int wm = warp & 3, wn = warp >> 2;
    const __half* A = g_xnh + (size_t)m0 * D_;
    const __half* W = g_wh + ((size_t)t * H_ + h) * D_ * E_;
    float acc[2][16][4];
    hgemm_main(A, D_, W, 4, smem, acc);

    if (t != 2) {
        __half* C = (t == 0 ? g_qh : t == 1 ? g_kh : g_gth) + (size_t)h * M_ * E_;
        #pragma unroll
        for (int mi = 0; mi < 2; mi++){
            int r0 = m0 + wm * 32 + mi * 16 + (lane >> 2), r1 = r0 + 8;
            #pragma unroll
            for (int nb = 0; nb < 8; nb++)
                #pragma unroll
                for (int t2 = 0; t2 < 2; t2++){
                    int col = wn * 128 + nb * 16 + t2 * 8 + (lane & 3) * 2;
                    const float* a = acc[mi][nb * 2 + t2];
                    *(__half2*)&C[(size_t)r0 * E_ + col] = __floats2half2_rn(a[0], a[1]);
                    *(__half2*)&C[(size_t)r1 * E_ + col] = __floats2half2_rn(a[2], a[3]);
                }
        }
    } else {
        __half* st = (__half*)smem;
        #pragma unroll
        for (int mi = 0; mi < 2; mi++){
            int r0 = wm * 32 + mi * 16 + (lane >> 2), r1 = r0 + 8;
            #pragma unroll
            for (int nb = 0; nb < 8; nb++)
                #pragma unroll
                for (int t2 = 0; t2 < 2; t2++){
                    int col = wn * 128 + nb * 16 + t2 * 8 + (lane & 3) * 2;
                    const float* a = acc[mi][nb * 2 + t2];
                    st[(col    ) * VT_LDT + r0] = __float2half_rn(a[0]);
                    st[(col + 1) * VT_LDT + r0] = __float2half_rn(a[1]);
                    st[(col    ) * VT_LDT + r1] = __float2half_rn(a[2]);
                    st[(col + 1) * VT_LDT + r1] = __float2half_rn(a[3]);
                }
        }
        __syncthreads();
        const int bidx = m0 >> 11, n0 = m0 & (N_ - 1);
        __half* dst = g_vt + (size_t)(h * B_ + bidx) * E_ * N_;
        #pragma unroll
        for (int i = 0; i < 16; i++){
            int chunk = tid + i * 256;
            int e = chunk >> 4, off = (chunk & 15) * 8;
            *(uint4*)&dst[(size_t)e * N_ + n0 + off] = *(uint4*)&st[e * VT_LDT + off];
        }
    }
}

// =================== K3: HMMA flash attention (m32 warp tiles) ===============
#define LDK 264
#define LDV 72
#define LDP 72
#define AT_Q   0
#define AT_K   (128 * LDK)                 // 2 bufs of 64*LDK
#define AT_V   (AT_K + 2 * 64 * LDK)       // 2 bufs of 256*LDV
#define AT_P   (AT_V + 2 * 256 * LDV)      // 128*LDP
#define AT_ONE (AT_P + 128 * LDP)          // 8*LDP (row0=ones, rows1-7=0)
#define AT_KM  (AT_ONE + 8 * LDP)          // 64 halves
#define AT_L   (AT_KM + 64)                // 128 floats = 256 halves
#define AT_H   (AT_L + 256)
#define AT_SMEM (AT_H * 2)                 // 229120 bytes

__global__ void __launch_bounds__(256, 1) attn_mma_k(const float* __restrict__ mask)
{
    extern __shared__ __half sm[];
    const int tid = threadIdx.x, lane = tid & 31, warp = tid >> 5;
    const int wm = warp & 3, wt = warp >> 2;      // wt: n32-group (S) / e128-group (PV)
    const int qt = blockIdx.x, hb = blockIdx.y, bidx = hb & (B_ - 1);
    const int qbase = qt * 128;
    const __half* Qg = g_qh + (size_t)hb * N_ * E_ + (size_t)qbase * E_;
    const __half* Kg = g_kh + (size_t)hb * N_ * E_;
    const __half* Vt = g_vt + (size_t)hb * E_ * N_;
    __half* Og = g_oh + (size_t)hb * N_ * E_;
    const float* mrow = mask + (size_t)bidx * N_;

    const uint32_t sQ = s2u(sm + AT_Q);
    const uint32_t sK = s2u(sm + AT_K);
    const uint32_t sV = s2u(sm + AT_V);
    const uint32_t sP = s2u(sm + AT_P);
    const uint32_t sONE = s2u(sm + AT_ONE);
    uint32_t* kmarr = (uint32_t*)(sm + AT_KM);
    float* l_sm = (float*)(sm + AT_L);

    // ones region: row0 = 1.0h x 72, rows 1-7 = 0
    if (tid < 288) ((uint32_t*)(sm + AT_ONE))[tid] = (tid < 36) ? 0x3C003C00u : 0u;

    // prologue: Q; K0+V0 (group), K1+V1 (group)
    #pragma unroll
    for (int it = 0; it < 16; it++) {
        int idx = tid + it * 256;
        int row = idx >> 5, c = idx & 31;
        cp16(sQ + (uint32_t)(row * LDK + c * 8) * 2, Qg + (size_t)row * E_ + c * 8);
    }
    #pragma unroll
    for (int buf = 0; buf < 2; buf++) {
        #pragma unroll
        for (int it = 0; it < 8; it++) {
            int idx = tid + it * 256;
            int row = idx >> 5, c = idx & 31;
            cp16(sK + (uint32_t)(buf * 64 * LDK + row * LDK + c * 8) * 2,
                 Kg + (size_t)(buf * 64 + row) * E_ + c * 8);
        }
        #pragma unroll
        for (int it = 0; it < 8; it++) {
            int idx = tid + it * 256;
            int e = idx >> 3, c = idx & 7;
            cp16(sV + (uint32_t)(buf * 256 * LDV + e * LDV + c * 8) * 2,
                 Vt + (size_t)e * N_ + buf * 64 + c * 8);
        }
        cp_commit();
    }

    const int grp = lane >> 3, r8 = lane & 7;
    const int moff = (grp & 2) ? 8 : 0;
    const int koff = (grp & 1) ? 8 : 0;
    uint32_t qaddr[2], paddr[2], kaddr[2];
    #pragma unroll
    for (int mi = 0; mi < 2; mi++){
        qaddr[mi] = sQ + (uint32_t)((wm * 32 + mi * 16 + (lane & 15)) * LDK + (lane >> 4) * 8) * 2;
        paddr[mi] = sP + (uint32_t)((wm * 32 + mi * 16 + (lane & 15)) * LDP + (lane >> 4) * 8) * 2;
    }
    #pragma unroll
    for (int nj = 0; nj < 2; nj++)
        kaddr[nj] = sK + (uint32_t)((wt * 32 + nj * 16 + moff + r8) * LDK + koff) * 2;
    const uint32_t vaddr = sV + (uint32_t)((wt * 128 + moff + r8) * LDV + koff) * 2;
    const uint32_t exaddr = sONE + (uint32_t)((lane & 7) * LDP + ((lane >> 3) & 1) * 8) * 2;

    float acc[2][16][4];
    #pragma unroll
    for (int mi = 0; mi < 2; mi++)
        #pragma unroll
        for (int i = 0; i < 16; i++)
            #pragma unroll
            for (int j = 0; j < 4; j++) acc[mi][i][j] = 0.f;
    float Oex[2][4] = {{0.f,0.f,0.f,0.f},{0.f,0.f,0.f,0.f}};

    for (int kc = 0; kc < 32; kc++) {
        if (kc == 31) cp_wait<0>(); else cp_wait<1>();
        const int kb = kc * 64;
        if (tid < 32) {
            float a = mrow[kb + tid * 2], b = mrow[kb + tid * 2 + 1];
            __half2 km = __floats2half2_rn((a == PADV) ? 0.f : 1.f, (b == PADV) ? 0.f : 1.f);
            kmarr[tid] = *(uint32_t*)&km;
        }
        __syncthreads();
        const uint32_t kbufo = (uint32_t)((kc & 1) * 64 * LDK * 2);
        const uint32_t vbufo = (uint32_t)((kc & 1) * 256 * LDV * 2);

        // ---- S = Q K^T : warp tile m32 x n32 ----
        float S[2][4][4];
        #pragma unroll
        for (int mi = 0; mi < 2; mi++)
            #pragma unroll
            for (int i = 0; i < 4; i++)
                #pragma unroll
                for (int j = 0; j < 4; j++) S[mi][i][j] = 0.f;

        #pragma unroll
        for (int ks = 0; ks < 16; ks++) {
            uint32_t a[2][4];
            #pragma unroll
            for (int mi = 0; mi < 2; mi++)
                ldsm_x4(a[mi][0], a[mi][1], a[mi][2], a[mi][3], qaddr[mi] + (uint32_t)(ks * 32));
            #pragma unroll
            for (int nj = 0; nj < 2; nj++) {
                uint32_t b0, b1, b2, b3;
                ldsm_x4(b0, b1, b2, b3, kaddr[nj] + kbufo + (uint32_t)(ks * 32));
                #pragma unroll
                for (int mi = 0; mi < 2; mi++){
                    mma16816(S[mi][nj * 2],     a[mi][0], a[mi][1], a[mi][2], a[mi][3], b0, b1);
                    mma16816(S[mi][nj * 2 + 1], a[mi][0], a[mi][1], a[mi][2], a[mi][3], b2, b3);
                }
            }
        }

        // ---- softmax -> P (fp16) to SMEM ----
        __half* Pp = sm + AT_P;
        #pragma unroll
        for (int mi = 0; mi < 2; mi++){
            int r0 = wm * 32 + mi * 16 + (lane >> 2);
            #pragma unroll
            for (int jj = 0; jj < 4; jj++){
                uint32_t km = kmarr[wt * 16 + jj * 4 + (lane & 3)];
                uint32_t p01 = mulh2(ex2h2(pack2(S[mi][jj][1] * CL2E, S[mi][jj][0] * CL2E)), km);
                uint32_t p23 = mulh2(ex2h2(pack2(S[mi][jj][3] * CL2E, S[mi][jj][2] * CL2E)), km);
                int cc = wt * 32 + jj * 8 + (lane & 3) * 2;
                *(uint32_t*)(Pp + r0 * LDP + cc)       = p01;
                *(uint32_t*)(Pp + (r0 + 8) * LDP + cc) = p23;
            }
        }
        __syncthreads();

        // K prefetch for kc+2 (K-buf reads for this chunk are complete)
        if (kc + 2 < 32) {
            const int nb2 = kb + 128;
            #pragma unroll
            for (int it = 0; it < 8; it++) {
                int idx = tid + it * 256;
                int row = idx >> 5, c = idx & 31;
                cp16(sK + (uint32_t)((kc & 1) * 64 * LDK + row * LDK + c * 8) * 2,
                     Kg + (size_t)(nb2 + row) * E_ + c * 8);
            }
        }

        // ---- O += P V : warp tile m32 x e128 ----
        #pragma unroll
        for (int ks = 0; ks < 4; ks++) {
            uint32_t pa[2][4];
            #pragma unroll
            for (int mi = 0; mi < 2; mi++)
                ldsm_x4(pa[mi][0], pa[mi][1], pa[mi][2], pa[mi][3], paddr[mi] + (uint32_t)(ks * 32));
            #pragma unroll
            for (int nb = 0; nb < 8; nb++) {
                uint32_t v0, v1, v2, v3;
                ldsm_x4(v0, v1, v2, v3, vaddr + vbufo + (uint32_t)(nb * 16 * LDV * 2 + ks * 32));
                #pragma unroll
                for (int mi = 0; mi < 2; mi++){
                    mma16816(acc[mi][nb * 2],     pa[mi][0], pa[mi][1], pa[mi][2], pa[mi][3], v0, v1);
                    mma16816(acc[mi][nb * 2 + 1], pa[mi][0], pa[mi][1], pa[mi][2], pa[mi][3], v2, v3);
                }
            }
            if (wt) {
                uint32_t e0, e1;
                ldsm_x2(e0, e1, exaddr + (uint32_t)(ks * 32));
                #pragma unroll
                for (int mi = 0; mi < 2; mi++)
                    mma16816(Oex[mi], pa[mi][0], pa[mi][1], pa[mi][2], pa[mi][3], e0, e1);
            }
        }
        __syncthreads();

        // V prefetch for kc+2; commit K+V as one group
        if (kc + 2 < 32) {
            const int nb2 = kb + 128;
            #pragma unroll
            for (int it = 0; it < 8; it++) {
                int idx = tid + it * 256;
                int e = idx >> 3, c = idx & 7;
                cp16(sV + (uint32_t)((kc & 1) * 256 * LDV + e * LDV + c * 8) * 2,
                     Vt + (size_t)e * N_ + nb2 + c * 8);
            }
            cp_commit();
        }
    }

    // ---- finalize: l via SMEM, normalize, write ----
    if (wt && (lane & 3) == 0) {
        #pragma unroll
        for (int mi = 0; mi < 2; mi++){
            int r = wm * 32 + mi * 16 + (lane >> 2);
            l_sm[r]     = Oex[mi][0];
            l_sm[r + 8] = Oex[mi][2];
        }
    }
    __syncthreads();
    #pragma unroll
    for (int mi = 0; mi < 2; mi++){
        int rl0 = wm * 32 + mi * 16 + (lane >> 2), rl1 = rl0 + 8;
        int r0 = qbase + rl0, r1 = qbase + rl1;
        float inv0 = ((mrow[r0] == PADV) ? 0.f : 1.f) / fmaxf(l_sm[rl0], 1e-30f);
        float inv1 = ((mrow[r1] == PADV) ? 0.f : 1.f) / fmaxf(l_sm[rl1], 1e-30f);
        #pragma unroll
        for (int nb = 0; nb < 8; nb++)
            #pragma unroll
            for (int t2 = 0; t2 < 2; t2++){
                int col = wt * 128 + nb * 16 + t2 * 8 + (lane & 3) * 2;
                const float* a = acc[mi][nb * 2 + t2];
                *(__half2*)&Og[(size_t)r0 * E_ + col] = __floats2half2_rn(a[0] * inv0, a[1] * inv0);
                *(__half2*)&Og[(size_t)r1 * E_ + col] = __floats2half2_rn(a[2] * inv1, a[3] * inv1);
            }
    }
}

// ---------------- K4: gate + residual + per-head LN + concat (warp/row) -----
__global__ void __launch_bounds__(256) epi_k(const float* __restrict__ x,
                      const float* __restrict__ gr, const float* __restrict__ br)
{
    int row = blockIdx.x * 8 + (threadIdx.x >> 5);   // row = m*4 + h
    int lane = threadIdx.x & 31;
    int m = row >> 2, h = row & 3;
    size_t off = ((size_t)h * M_ + m) * E_ + lane * 8;
    uint4 ou = *(uint4*)(g_oh + off);
    uint4 gu = *(uint4*)(g_gth + off);
    const float4* xr = (const float4*)(x + (size_t)m * D_) + lane * 2;
    float4 x0 = xr[0], x1 = xr[1];
    float xv[8] = {x0.x, x0.y, x0.z, x0.w, x1.x, x1.y, x1.z, x1.w};
    float t[8];
    const uint32_t* op = (const uint32_t*)&ou;
    const uint32_t* gp = (const uint32_t*)&gu;
    float s = 0.f, s2 = 0.f;
    #pragma unroll
    for (int j = 0; j < 4; j++) {
        float2 o2 = __half22float2(*(const __half2*)&op[j]);
        float2 g2 = __half22float2(*(const __half2*)&gp[j]);
        float sg0 = 1.f / (1.f + __expf(-g2.x));
        float sg1 = 1.f / (1.f + __expf(-g2.y));
        t[2*j]   = o2.x * sg0 + xv[2*j];
        t[2*j+1] = o2.y * sg1 + xv[2*j+1];
        s += t[2*j] + t[2*j+1];
        s2 += t[2*j]*t[2*j] + t[2*j+1]*t[2*j+1];
    }
    float mean, var; warp_meanvar(s, s2, mean, var);
    float rs = rsqrtf(var + EPS_);
    float4 gr0 = ((const float4*)gr)[lane*2], gr1 = ((const float4*)gr)[lane*2+1];
    float4 br0 = ((const float4*)br)[lane*2], br1 = ((const float4*)br)[lane*2+1];
    float grv[8] = {gr0.x, gr0.y, gr0.z, gr0.w, gr1.x, gr1.y, gr1.z, gr1.w};
    float brv[8] = {br0.x, br0.y, br0.z, br0.w, br1.x, br1.y, br1.z, br1.w};
    uint32_t outv[4];
    #pragma unroll
    for (int j = 0; j < 4; j++)
        outv[j] = pack2((t[2*j+1]-mean)*rs*grv[2*j+1]+brv[2*j+1],
                        (t[2*j]  -mean)*rs*grv[2*j]  +brv[2*j]);
    *(uint4*)(g_yh + (size_t)m * (H_ * E_) + h * E_ + lane * 8) = *(uint4*)outv;
}

// ---------------- K5: output projection (HMMA) + bias + residual ------------
__global__ void __launch_bounds__(256, 1) outproj_h_k(
    const float* __restrict__ out_b, const float* __restrict__ x)
{
    extern __shared__ char smem[];
    const int m0 = blockIdx.x * 128;
    const int tid = threadIdx.x, lane = tid & 31, warp = tid >> 5;
    const int wm = warp & 3, wn = warp >> 2;
    const __half* A = g_yh + (size_t)m0 * (H_ * E_);
    float acc[2][16][4];
    hgemm_main(A, H_ * E_, g_w1h, 16, smem, acc);

    #pragma unroll
    for (int mi = 0; mi < 2; mi++){
        int r0 = m0 + wm * 32 + mi * 16 + (lane >> 2), r1 = r0 + 8;
        #pragma unroll
        for (int nb = 0; nb < 8; nb++)
            #pragma unroll
            for (int t2 = 0; t2 < 2; t2++){
                int col = wn * 128 + nb * 16 + t2 * 8 + (lane & 3) * 2;
                const float* a = acc[mi][nb * 2 + t2];
                float b0 = out_b[col], b1 = out_b[col + 1];
                float2 x0 = *(const float2*)&x[(size_t)r0 * D_ + col];
                float2 x1 = *(const float2*)&x[(size_t)r1 * D_ + col];
                *(float2*)&g_z[(size_t)r0 * E_ + col] = make_float2(a[0] + b0 + x0.x, a[1] + b1 + x0.y);
                *(float2*)&g_z[(size_t)r1 * E_ + col] = make_float2(a[2] + b0 + x1.x, a[3] + b1 + x1.y);
            }
    }
}

// ---------------- K6: final LN * mask (warp per row) -------------------------
__global__ void __launch_bounds__(256) final_k(const float* __restrict__ mask,
                        const float* __restrict__ go, const float* __restrict__ bo,
                        float* __restrict__ out)
{
    int row = blockIdx.x * 8 + (threadIdx.x >> 5);
    int lane = threadIdx.x & 31;
    const float4* zr = (const float4*)(g_z + (size_t)row * E_) + lane * 2;
    float4 v0 = zr[0], v1 = zr[1];
    float s  = v0.x + v0.y + v0.z + v0.w + v1.x + v1.y + v1.z + v1.w;
    float s2 = v0.x*v0.x + v0.y*v0.y + v0.z*v0.z + v0.w*v0.w
             + v1.x*v1.x + v1.y*v1.y + v1.z*v1.z + v1.w*v1.w;
    float mean, var; warp_meanvar(s, s2, mean, var);
    float rs = rsqrtf(var + EPS_);
    float mv = (mask[row] == PADV) ? 0.f : 1.f;
    float4 g0 = ((const float4*)go)[lane*2], g1 = ((const float4*)go)[lane*2+1];
    float4 b0 = ((const float4*)bo)[lane*2], b1 = ((const float4*)bo)[lane*2+1];
    float4 r0, r1;
    r0.x = ((v0.x-mean)*rs*g0.x+b0.x)*mv; r0.y = ((v0.y-mean)*rs*g0.y+b0.y)*mv;
    r0.z = ((v0.z-mean)*rs*g0.z+b0.z)*mv; r0.w = ((v0.w-mean)*rs*g0.w+b0.w)*mv;
    r1.x = ((v1.x-mean)*rs*g1.x+b1.x)*mv; r1.y = ((v1.y-mean)*rs*g1.y+b1.y)*mv;
    r1.z = ((v1.z-mean)*rs*g1.z+b1.z)*mv; r1.w = ((v1.w-mean)*rs*g1.w+b1.w)*mv;
    float4* orow = (float4*)(out + (size_t)row * E_) + lane * 2;
    orow[0] = r0; orow[1] = r1;
}

// ---------------- launch ------------------------------------------------------
extern "C" void kernel_launch(void* const* d_in, const int* in_sizes, int n_in,
                              void* d_out, int out_size)
{
    (void)in_sizes; (void)n_in; (void)out_size;
    const float* x     = (const float*)d_in[0];
    const float* mask  = (const float*)d_in[1];
    const float* Wq    = (const float*)d_in[2];
    const float* Wk    = (const float*)d_in[3];
    const float* Wv    = (const float*)d_in[4];
    const float* Wg    = (const float*)d_in[5];
    const float* out_w = (const float*)d_in[6];
    const float* out_b = (const float*)d_in[7];
    const float* g_in  = (const float*)d_in[8];
    const float* b_in  = (const float*)d_in[9];
    const float* g_res = (const float*)d_in[10];
    const float* b_res = (const float*)d_in[11];
    const float* g_out = (const float*)d_in[12];
    const float* b_out = (const float*)d_in[13];
    float* out = (float*)d_out;

    cudaFuncSetAttribute(attn_mma_k,  cudaFuncAttributeMaxDynamicSharedMemorySize, AT_SMEM);
    cudaFuncSetAttribute(qkvg_h_k,    cudaFuncAttributeMaxDynamicSharedMemorySize, HG_SMEM);
    cudaFuncSetAttribute(outproj_h_k, cudaFuncAttributeMaxDynamicSharedMemorySize, HG_SMEM);

    ln_in_k<<<M_ / 8, 256>>>(x, g_in, b_in);
    wconv_k<<<dim3(H_ * D_ * E_ / 1024, 5), 256>>>(Wq, Wk, Wv, Wg, out_w);

    dim3 g2(M_ / 128, HB_);                    // (64, 16)
    qkvg_h_k<<<g2, 256, HG_SMEM>>>();

    dim3 g3(N_ / 128, HB_);                    // (16, 16)
    attn_mma_k<<<g3, 256, AT_SMEM>>>(mask);

    epi_k<<<M_ * H_ / 8, 256>>>(x, g_res, b_res);

    outproj_h_k<<<M_ / 128, 256, HG_SMEM>>>(out_b, x);

    final_k<<<M_ / 8, 256>>>(mask, g_out, b_out, out);
}

// round 7
// speedup vs baseline: 8.8748x; 1.0351x over previous
#include <cuda_runtime.h>
#include <cuda_fp16.h>
#include <math.h>
#include <stdint.h>

#define B_  4
#define N_  2048
#define D_  256
#define H_  4
#define E_  256
#define M_  (B_*N_)          // 8192 rows
#define HB_ (H_*B_)          // 16
#define PADV (-2.0f)
#define EPS_ 1e-6f
#define CL2E 0.09016844f     // (1/sqrt(256)) * log2(e)

// ---------------- scratch (device globals; no runtime alloc) ----------------
__device__ __half g_xnh[(size_t)M_*D_];          // LN(x) fp16
__device__ __half g_qh [(size_t)HB_*N_*E_];      // Q fp16 [h][m][e]
__device__ __half g_kh [(size_t)HB_*N_*E_];      // K fp16 [h][m][e]
__device__ __half g_vt [(size_t)HB_*E_*N_];      // V^T fp16 [h][b][e][n]
__device__ __half g_gth[(size_t)HB_*N_*E_];      // gate pre-activation fp16
__device__ __half g_oh [(size_t)HB_*N_*E_];      // attention output fp16
__device__ __half g_yh [(size_t)M_*H_*E_];       // concat fp16 [m][h*E+e]
__device__ float  g_z  [(size_t)M_*E_];          // pre-final-LN fp32
__device__ __half g_wh [(size_t)4*H_*D_*E_];     // qkvg weights fp16 [t][h][d][e]
__device__ __half g_w1h[(size_t)H_*E_*E_];       // out_w fp16, rows permuted to [h*E+e]

// =================== PTX helpers (compute_103-safe) ===================
__device__ __forceinline__ uint32_t s2u(const void* p){
    uint32_t a;
    asm("{ .reg .u64 t; cvta.to.shared.u64 t, %1; cvt.u32.u64 %0, t; }" : "=r"(a) : "l"(p));
    return a;
}
__device__ __forceinline__ void cp16(uint32_t s, const void* g){
    asm volatile("cp.async.cg.shared.global [%0], [%1], 16;" :: "r"(s), "l"(g));
}
__device__ __forceinline__ void cp_commit(){ asm volatile("cp.async.commit_group;" ::: "memory"); }
template<int NN> __device__ __forceinline__ void cp_wait(){
    asm volatile("cp.async.wait_group %0;" :: "n"(NN) : "memory");
}
__device__ __forceinline__ void ldsm_x4(uint32_t& r0, uint32_t& r1, uint32_t& r2, uint32_t& r3, uint32_t addr){
    asm volatile("ldmatrix.sync.aligned.m8n8.x4.shared.b16 {%0,%1,%2,%3}, [%4];"
        : "=r"(r0), "=r"(r1), "=r"(r2), "=r"(r3) : "r"(addr));
}
__device__ __forceinline__ void ldsm_x2(uint32_t& r0, uint32_t& r1, uint32_t addr){
    asm volatile("ldmatrix.sync.aligned.m8n8.x2.shared.b16 {%0,%1}, [%2];"
        : "=r"(r0), "=r"(r1) : "r"(addr));
}
__device__ __forceinline__ void ldsm_x4t(uint32_t& r0, uint32_t& r1, uint32_t& r2, uint32_t& r3, uint32_t addr){
    asm volatile("ldmatrix.sync.aligned.m8n8.x4.trans.shared.b16 {%0,%1,%2,%3}, [%4];"
        : "=r"(r0), "=r"(r1), "=r"(r2), "=r"(r3) : "r"(addr));
}
__device__ __forceinline__ void mma16816(float c[4], uint32_t a0, uint32_t a1, uint32_t a2, uint32_t a3,
                                         uint32_t b0, uint32_t b1){
    asm volatile("mma.sync.aligned.m16n8k16.row.col.f32.f16.f16.f32 "
        "{%0,%1,%2,%3}, {%4,%5,%6,%7}, {%8,%9}, {%0,%1,%2,%3};"
        : "+f"(c[0]), "+f"(c[1]), "+f"(c[2]), "+f"(c[3])
        : "r"(a0), "r"(a1), "r"(a2), "r"(a3), "r"(b0), "r"(b1));
}
__device__ __forceinline__ uint32_t pack2(float hi, float lo){
    uint32_t d; asm("cvt.rn.f16x2.f32 %0, %1, %2;" : "=r"(d) : "f"(hi), "f"(lo)); return d;
}
__device__ __forceinline__ uint32_t ex2h2(uint32_t a){
    uint32_t d; asm("ex2.approx.f16x2 %0, %1;" : "=r"(d) : "r"(a)); return d;
}
__device__ __forceinline__ uint32_t mulh2(uint32_t a, uint32_t b){
    uint32_t d; asm("mul.f16x2 %0, %1, %2;" : "=r"(d) : "r"(a), "r"(b)); return d;
}

// ---------------- warp row-reduction helper ----------------------------------
__device__ __forceinline__ void warp_meanvar(float s, float s2, float& mean, float& var){
    #pragma unroll
    for (int o = 16; o; o >>= 1) {
        s  += __shfl_xor_sync(0xffffffffu, s,  o);
        s2 += __shfl_xor_sync(0xffffffffu, s2, o);
    }
    mean = s * (1.0f / 256.0f);
    var  = s2 * (1.0f / 256.0f) - mean * mean;
}

// ---------------- K1: input LN (warp per row, fp16 out) ----------------------
__global__ void __launch_bounds__(256) ln_in_k(const float* __restrict__ x,
                        const float* __restrict__ g, const float* __restrict__ b) {
    int row = blockIdx.x * 8 + (threadIdx.x >> 5);
    int lane = threadIdx.x & 31;
    const float4* xr = (const float4*)(x + (size_t)row * D_) + lane * 2;
    float4 v0 = xr[0], v1 = xr[1];
    float s  = v0.x + v0.y + v0.z + v0.w + v1.x + v1.y + v1.z + v1.w;
    float s2 = v0.x*v0.x + v0.y*v0.y + v0.z*v0.z + v0.w*v0.w
             + v1.x*v1.x + v1.y*v1.y + v1.z*v1.z + v1.w*v1.w;
    float mean, var; warp_meanvar(s, s2, mean, var);
    float rs = rsqrtf(var + EPS_);
    float4 g0 = ((const float4*)g)[lane*2], g1 = ((const float4*)g)[lane*2+1];
    float4 b0 = ((const float4*)b)[lane*2], b1 = ((const float4*)b)[lane*2+1];
    uint32_t o[4];
    o[0] = pack2((v0.y-mean)*rs*g0.y+b0.y, (v0.x-mean)*rs*g0.x+b0.x);
    o[1] = pack2((v0.w-mean)*rs*g0.w+b0.w, (v0.z-mean)*rs*g0.z+b0.z);
    o[2] = pack2((v1.y-mean)*rs*g1.y+b1.y, (v1.x-mean)*rs*g1.x+b1.x);
    o[3] = pack2((v1.w-mean)*rs*g1.w+b1.w, (v1.z-mean)*rs*g1.z+b1.z);
    *(uint4*)(g_xnh + (size_t)row * D_ + lane * 8) = *(uint4*)o;
}

// ---------------- K1b: weight conversion fp32 -> fp16 (+out_w row permute) --
__global__ void wconv_k(const float* __restrict__ Wq, const float* __restrict__ Wk,
                        const float* __restrict__ Wv, const float* __restrict__ Wg,
                        const float* __restrict__ ow) {
    int t = blockIdx.y;
    const float* src = (t == 0) ? Wq : (t == 1) ? Wk : (t == 2) ? Wv : (t == 3) ? Wg : ow;
    int idx = (blockIdx.x * 256 + threadIdx.x) * 4;
    float4 v = *(const float4*)(src + idx);
    __half2 h0 = __floats2half2_rn(v.x, v.y), h1 = __floats2half2_rn(v.z, v.w);
    if (t < 4) {
        __half2* d2 = (__half2*)(g_wh + (size_t)t * (H_ * D_ * E_) + idx);
        d2[0] = h0; d2[1] = h1;
    } else {
        int rr = idx >> 8, col = idx & 255;       // src row = e*H + h
        int e = rr >> 2, h = rr & 3;
        __half2* d2 = (__half2*)(g_w1h + (size_t)(h * E_ + e) * E_ + col);
        d2[0] = h0; d2[1] = h1;
    }
}

// =================== HMMA GEMM mainloop: 128 x 256 tile, m32n128/warp ========
#define HG_LDA 72
#define HG_LDB 264
#define HG_BS_OFF 36864
#define HG_SMEM 104448
#define VT_LDT 136

__device__ __forceinline__ void hg_load(const __half* A, int ldA, const __half* Bg,
                                        uint32_t sA, uint32_t sB, int c, int buf, int tid){
    #pragma unroll
    for (int it = 0; it < 4; it++){
        int idx = tid + it * 256;
        int row = idx >> 3, cg = idx & 7;
        cp16(sA + (uint32_t)(buf * 128 * HG_LDA + row * HG_LDA + cg * 8) * 2,
             A + (size_t)row * ldA + c * 64 + cg * 8);
    }
    #pragma unroll
    for (int it = 0; it < 8; it++){
        int idx = tid + it * 256;
        int row = idx >> 5, cg = idx & 31;
        cp16(sB + (uint32_t)(buf * 64 * HG_LDB + row * HG_LDB + cg * 8) * 2,
             Bg + (size_t)(c * 64 + row) * 256 + cg * 8);
    }
    cp_commit();
}

__device__ __forceinline__ void hgemm_main(const __half* A, int ldA, const __half* Bg,
                                           int NC, char* smem, float acc[2][16][4]){
    const int tid = threadIdx.x, lane = tid & 31, warp = tid >> 5;
    const int wm = warp & 3, wn = warp >> 2;
    const uint32_t sA = s2u(smem), sB = s2u(smem + HG_BS_OFF);
    #pragma unroll
    for (int mi = 0; mi < 2; mi++)
        #pragma unroll
        for (int i = 0; i < 16; i++)
            #pragma unroll
            for (int j = 0; j < 4; j++) acc[mi][i][j] = 0.f;

    hg_load(A, ldA, Bg, sA, sB, 0, 0, tid);
    hg_load(A, ldA, Bg, sA, sB, 1, 1, tid);

    const int grp = lane >> 3, r8 = lane & 7;
    uint32_t aoff[2];
    #pragma unroll
    for (int mi = 0; mi < 2; mi++)
        aoff[mi] = (uint32_t)((wm * 32 + mi * 16 + (lane & 15)) * HG_LDA + (lane >> 4) * 8) * 2;
    const uint32_t boff = (uint32_t)(((grp & 1) * 8 + r8) * HG_LDB + wn * 128 + ((grp & 2) ? 8 : 0)) * 2;

    for (int c = 0; c < NC; c++){
        if (c + 1 < NC) cp_wait<1>(); else cp_wait<0>();
        __syncthreads();
        const uint32_t sa = sA + (uint32_t)((c & 1) * 128 * HG_LDA * 2);
        const uint32_t sb = sB + (uint32_t)((c & 1) * 64 * HG_LDB * 2) + boff;
        #pragma unroll
        for (int ks = 0; ks < 4; ks++){
            uint32_t a[2][4];
            #pragma unroll
            for (int mi = 0; mi < 2; mi++)
                ldsm_x4(a[mi][0], a[mi][1], a[mi][2], a[mi][3], sa + aoff[mi] + (uint32_t)(ks * 32));
            #pragma unroll
            for (int nb = 0; nb < 8; nb++){
                uint32_t b0, b1, b2, b3;
                ldsm_x4t(b0, b1, b2, b3, sb + (uint32_t)(ks * 16 * HG_LDB + nb * 16) * 2);
                #pragma unroll
                for (int mi = 0; mi < 2; mi++){
                    mma16816(acc[mi][2 * nb],     a[mi][0], a[mi][1], a[mi][2], a[mi][3], b0, b1);
                    mma16816(acc[mi][2 * nb + 1], a[mi][0], a[mi][1], a[mi][2], a[mi][3], b2, b3);
                }
            }
        }
        __syncthreads();
        if (c + 2 < NC) hg_load(A, ldA, Bg, sA, sB, c + 2, c & 1, tid);
    }
}

// ---------------- K2: Q/K/V/gate projections (HMMA) --------------------------
__global__ void __launch_bounds__(256, 1) qkvg_h_k()
{
    extern __shared__ char smem[];
    const int z = blockIdx.y, h = z >> 2, t = z & 3;
    const int m0 = blockIdx.x * 128;
    const int tid = threadIdx.x, lane = tid & 31, warp = tid >> 5;
    const int wm = warp & 3, wn = warp >> 2;
    const __half* A = g_xnh + (size_t)m0 * D_;
    const __half* W = g_wh + ((size_t)t * H_ + h) * D_ * E_;
    float acc[2][16][4];
    hgemm_main(A, D_, W, 4, smem, acc);

    if (t != 2) {
        __half* C = (t == 0 ? g_qh : t == 1 ? g_kh : g_gth) + (size_t)h * M_ * E_;
        #pragma unroll
        for (int mi = 0; mi < 2; mi++){
            int r0 = m0 + wm * 32 + mi * 16 + (lane >> 2), r1 = r0 + 8;
            #pragma unroll
            for (int nb = 0; nb < 8; nb++)
                #pragma unroll
                for (int t2 = 0; t2 < 2; t2++){
                    int col = wn * 128 + nb * 16 + t2 * 8 + (lane & 3) * 2;
                    const float* a = acc[mi][nb * 2 + t2];
                    *(__half2*)&C[(size_t)r0 * E_ + col] = __floats2half2_rn(a[0], a[1]);
                    *(__half2*)&C[(size_t)r1 * E_ + col] = __floats2half2_rn(a[2], a[3]);
                }
        }
    } else {
        __half* st = (__half*)smem;
        #pragma unroll
        for (int mi = 0; mi < 2; mi++){
            int r0 = wm * 32 + mi * 16 + (lane >> 2), r1 = r0 + 8;
            #pragma unroll
            for (int nb = 0; nb < 8; nb++)
                #pragma unroll
                for (int t2 = 0; t2 < 2; t2++){
                    int col = wn * 128 + nb * 16 + t2 * 8 + (lane & 3) * 2;
                    const float* a = acc[mi][nb * 2 + t2];
                    st[(col    ) * VT_LDT + r0] = __float2half_rn(a[0]);
                    st[(col + 1) * VT_LDT + r0] = __float2half_rn(a[1]);
                    st[(col    ) * VT_LDT + r1] = __float2half_rn(a[2]);
                    st[(col + 1) * VT_LDT + r1] = __float2half_rn(a[3]);
                }
        }
        __syncthreads();
        const int bidx = m0 >> 11, n0 = m0 & (N_ - 1);
        __half* dst = g_vt + (size_t)(h * B_ + bidx) * E_ * N_;
        #pragma unroll
        for (int i = 0; i < 16; i++){
            int chunk = tid + i * 256;
            int e = chunk >> 4, off = (chunk & 15) * 8;
            *(uint4*)&dst[(size_t)e * N_ + n0 + off] = *(uint4*)&st[e * VT_LDT + off];
        }
    }
}

// =================== K3: HMMA flash attention (S/PV pipelined) ===============
#define LDK 264
#define LDV 72
#define AT_Q   0
#define AT_K   (128 * LDK)                 // 2 bufs of 64*LDK
#define AT_V   (AT_K + 2 * 64 * LDK)       // 2 bufs of 256*LDV
#define AT_ONE (AT_V + 2 * 256 * LDV)      // 8*LDV (row0=ones)
#define AT_KM  (AT_ONE + 8 * LDV)          // 2048 halves (1024 u32):全 key mask
#define AT_H   (AT_KM + 2048)
#define AT_SMEM (AT_H * 2)                 // 214144 bytes

// exp+mask: S[8][4] fp32 -> pa[4][4] fp16x2 A-fragments
__device__ __forceinline__ void expconv(const float S[8][4], uint32_t pa[4][4],
                                        const uint32_t* kmbase, int lane){
    #pragma unroll
    for (int nb = 0; nb < 8; nb++) {
        uint32_t km = kmbase[nb * 4 + (lane & 3)];
        uint32_t p01 = mulh2(ex2h2(pack2(S[nb][1] * CL2E, S[nb][0] * CL2E)), km);
        uint32_t p23 = mulh2(ex2h2(pack2(S[nb][3] * CL2E, S[nb][2] * CL2E)), km);
        pa[nb >> 1][(nb & 1) * 2]     = p01;
        pa[nb >> 1][(nb & 1) * 2 + 1] = p23;
    }
}

__global__ void __launch_bounds__(256, 1) attn_mma_k(const float* __restrict__ mask)
{
    extern __shared__ __half sm[];
    const int tid = threadIdx.x, lane = tid & 31, warp = tid >> 5;
    const int qt = blockIdx.x, hb = blockIdx.y, bidx = hb & (B_ - 1);
    const int qbase = qt * 128;
    const __half* Qg = g_qh + (size_t)hb * N_ * E_ + (size_t)qbase * E_;
    const __half* Kg = g_kh + (size_t)hb * N_ * E_;
    const __half* Vt = g_vt + (size_t)hb * E_ * N_;
    __half* Og = g_oh + (size_t)hb * N_ * E_;
    const float* mrow = mask + (size_t)bidx * N_;

    const uint32_t sQ = s2u(sm + AT_Q);
    const uint32_t sK = s2u(sm + AT_K);
    const uint32_t sV = s2u(sm + AT_V);
    const uint32_t sONE = s2u(sm + AT_ONE);
    uint32_t* kmarr = (uint32_t*)(sm + AT_KM);

    // ones region: row0 = 1.0h x 72, rows 1-7 = 0
    if (tid < 288) ((uint32_t*)(sm + AT_ONE))[tid] = (tid < 36) ? 0x3C003C00u : 0u;
    // key-mask for all 2048 keys (half2 packed)
    #pragma unroll
    for (int j = 0; j < 4; j++) {
        float a = mrow[tid * 8 + 2 * j], b = mrow[tid * 8 + 2 * j + 1];
        __half2 km = __floats2half2_rn((a == PADV) ? 0.f : 1.f, (b == PADV) ? 0.f : 1.f);
        kmarr[tid * 4 + j] = *(uint32_t*)&km;
    }

    // prologue: Q | K0 | V0 | K1 | V1 as 5 separate cp.async groups
    #pragma unroll
    for (int it = 0; it < 16; it++) {
        int idx = tid + it * 256;
        int row = idx >> 5, c = idx & 31;
        cp16(sQ + (uint32_t)(row * LDK + c * 8) * 2, Qg + (size_t)row * E_ + c * 8);
    }
    cp_commit();
    #pragma unroll
    for (int buf = 0; buf < 2; buf++) {
        #pragma unroll
        for (int it = 0; it < 8; it++) {
            int idx = tid + it * 256;
            int row = idx >> 5, c = idx & 31;
            cp16(sK + (uint32_t)(buf * 64 * LDK + row * LDK + c * 8) * 2,
                 Kg + (size_t)(buf * 64 + row) * E_ + c * 8);
        }
        cp_commit();
        #pragma unroll
        for (int it = 0; it < 8; it++) {
            int idx = tid + it * 256;
            int e = idx >> 3, c = idx & 7;
            cp16(sV + (uint32_t)(buf * 256 * LDV + e * LDV + c * 8) * 2,
                 Vt + (size_t)e * N_ + buf * 64 + c * 8);
        }
        cp_commit();
    }

    const int grp = lane >> 3, r8 = lane & 7;
    const int moff = (grp & 2) ? 8 : 0;
    const int koff = (grp & 1) ? 8 : 0;
    const uint32_t qaddr0 = sQ + (uint32_t)((warp * 16 + (lane & 15)) * LDK + (lane >> 4) * 8) * 2;
    const uint32_t kaddr0 = sK + (uint32_t)((moff + r8) * LDK + koff) * 2;
    const uint32_t vaddr0 = sV + (uint32_t)((moff + r8) * LDV + koff) * 2;
    const uint32_t exaddr = sONE + (uint32_t)((lane & 7) * LDV + ((lane >> 3) & 1) * 8) * 2;

    float O[32][4];
    #pragma unroll
    for (int i = 0; i < 32; i++)
        #pragma unroll
        for (int j = 0; j < 4; j++) O[i][j] = 0.f;
    float Oex[4] = {0.f, 0.f, 0.f, 0.f};
    uint32_t pa[4][4];

    // ---- preamble: S(0) -> pa ----
    cp_wait<3>();                 // Q + K0 complete
    __syncthreads();
    {
        float S[8][4];
        #pragma unroll
        for (int i = 0; i < 8; i++)
            #pragma unroll
            for (int j = 0; j < 4; j++) S[i][j] = 0.f;
        #pragma unroll
        for (int ks = 0; ks < 16; ks++) {
            uint32_t q0, q1, q2, q3;
            ldsm_x4(q0, q1, q2, q3, qaddr0 + (uint32_t)(ks * 32));
            #pragma unroll
            for (int nbp = 0; nbp < 4; nbp++) {
                uint32_t b0, b1, b2, b3;
                ldsm_x4(b0, b1, b2, b3, kaddr0 + (uint32_t)(nbp * 16 * LDK * 2 + ks * 32));
                mma16816(S[2 * nbp],     q0, q1, q2, q3, b0, b1);
                mma16816(S[2 * nbp + 1], q0, q1, q2, q3, b2, b3);
            }
        }
        expconv(S, pa, kmarr, lane);
    }

    // ---- main loop: PV(kc) interleaved with S(kc+1) ----
    for (int kc = 0; kc < 32; kc++) {
        if (kc == 31) cp_wait<0>(); else cp_wait<1>();   // K(kc+1) & V(kc) ready
        __syncthreads();
        const uint32_t kbN = kaddr0 + (uint32_t)(((kc + 1) & 1) * 64 * LDK) * 2;
        const uint32_t vb  = vaddr0 + (uint32_t)((kc & 1) * 256 * LDV) * 2;

        if (kc < 31) {
            float S[8][4];
            #pragma unroll
            for (int i = 0; i < 8; i++)
                #pragma unroll
                for (int j = 0; j < 4; j++) S[i][j] = 0.f;
            #pragma unroll
            for (int i = 0; i < 16; i++) {
                // S(kc+1) slice: k16 step i across all 64 next-keys
                uint32_t q0, q1, q2, q3;
                ldsm_x4(q0, q1, q2, q3, qaddr0 + (uint32_t)(i * 32));
                #pragma unroll
                for (int nbp = 0; nbp < 4; nbp++) {
                    uint32_t b0, b1, b2, b3;
                    ldsm_x4(b0, b1, b2, b3, kbN + (uint32_t)(nbp * 16 * LDK * 2 + i * 32));
                    mma16816(S[2 * nbp],     q0, q1, q2, q3, b0, b1);
                    mma16816(S[2 * nbp + 1], q0, q1, q2, q3, b2, b3);
                }
                // PV(kc) slice: e16 block i
                #pragma unroll
                for (int ks2 = 0; ks2 < 4; ks2++) {
                    uint32_t v0, v1, v2, v3;
                    ldsm_x4(v0, v1, v2, v3, vb + (uint32_t)(i * 16 * LDV * 2 + ks2 * 32));
                    mma16816(O[2 * i],     pa[ks2][0], pa[ks2][1], pa[ks2][2], pa[ks2][3], v0, v1);
                    mma16816(O[2 * i + 1], pa[ks2][0], pa[ks2][1], pa[ks2][2], pa[ks2][3], v2, v3);
                }
            }
            // row-sum via ones column (uses current pa)
            #pragma unroll
            for (int ks2 = 0; ks2 < 4; ks2++) {
                uint32_t e0, e1;
                ldsm_x2(e0, e1, exaddr + (uint32_t)(ks2 * 32));
                mma16816(Oex, pa[ks2][0], pa[ks2][1], pa[ks2][2], pa[ks2][3], e0, e1);
            }
            // P(kc+1)
            expconv(S, pa, kmarr + (kc + 1) * 32, lane);

            __syncthreads();
            if (kc + 2 < 32) {
                const int nb2 = kc * 64 + 128;
                #pragma unroll
                for (int it = 0; it < 8; it++) {
                    int idx = tid + it * 256;
                    int row = idx >> 5, c = idx & 31;
                    cp16(sK + (uint32_t)((kc & 1) * 64 * LDK + row * LDK + c * 8) * 2,
                         Kg + (size_t)(nb2 + row) * E_ + c * 8);
                }
                cp_commit();
                #pragma unroll
                for (int it = 0; it < 8; it++) {
                    int idx = tid + it * 256;
                    int e = idx >> 3, c = idx & 7;
                    cp16(sV + (uint32_t)((kc & 1) * 256 * LDV + e * LDV + c * 8) * 2,
                         Vt + (size_t)e * N_ + nb2 + c * 8);
                }
                cp_commit();
            }
        } else {
            // last chunk: PV only
            #pragma unroll
            for (int i = 0; i < 16; i++) {
                #pragma unroll
                for (int ks2 = 0; ks2 < 4; ks2++) {
                    uint32_t v0, v1, v2, v3;
                    ldsm_x4(v0, v1, v2, v3, vb + (uint32_t)(i * 16 * LDV * 2 + ks2 * 32));
                    mma16816(O[2 * i],     pa[ks2][0], pa[ks2][1], pa[ks2][2], pa[ks2][3], v0, v1);
                    mma16816(O[2 * i + 1], pa[ks2][0], pa[ks2][1], pa[ks2][2], pa[ks2][3], v2, v3);
                }
            }
            #pragma unroll
            for (int ks2 = 0; ks2 < 4; ks2++) {
                uint32_t e0, e1;
                ldsm_x2(e0, e1, exaddr + (uint32_t)(ks2 * 32));
                mma16816(Oex, pa[ks2][0], pa[ks2][1], pa[ks2][2], pa[ks2][3], e0, e1);
            }
        }
    }

    // ---- finalize: l from ones-column (quad broadcast), normalize, write ----
    float l0 = __shfl_sync(0xffffffffu, Oex[0], lane & ~3);
    float l1 = __shfl_sync(0xffffffffu, Oex[2], lane & ~3);
    const int r0 = qbase + warp * 16 + (lane >> 2);
    const int r1 = r0 + 8;
    float inv0 = ((mrow[r0] == PADV) ? 0.f : 1.f) / fmaxf(l0, 1e-30f);
    float inv1 = ((mrow[r1] == PADV) ? 0.f : 1.f) / fmaxf(l1, 1e-30f);
    #pragma unroll
    for (int eb = 0; eb < 32; eb++) {
        int col = eb * 8 + (lane & 3) * 2;
        *(__half2*)&Og[(size_t)r0 * E_ + col] = __floats2half2_rn(O[eb][0] * inv0, O[eb][1] * inv0);
        *(__half2*)&Og[(size_t)r1 * E_ + col] = __floats2half2_rn(O[eb][2] * inv1, O[eb][3] * inv1);
    }
}

// ---------------- K4: gate + residual + per-head LN + concat (warp/row) -----
__global__ void __launch_bounds__(256) epi_k(const float* __restrict__ x,
                      const float* __restrict__ gr, const float* __restrict__ br)
{
    int row = blockIdx.x * 8 + (threadIdx.x >> 5);   // row = m*4 + h
    int lane = threadIdx.x & 31;
    int m = row >> 2, h = row & 3;
    size_t off = ((size_t)h * M_ + m) * E_ + lane * 8;
    uint4 ou = *(uint4*)(g_oh + off);
    uint4 gu = *(uint4*)(g_gth + off);
    const float4* xr = (const float4*)(x + (size_t)m * D_) + lane * 2;
    float4 x0 = xr[0], x1 = xr[1];
    float xv[8] = {x0.x, x0.y, x0.z, x0.w, x1.x, x1.y, x1.z, x1.w};
    float t[8];
    const uint32_t* op = (const uint32_t*)&ou;
    const uint32_t* gp = (const uint32_t*)&gu;
    float s = 0.f, s2 = 0.f;
    #pragma unroll
    for (int j = 0; j < 4; j++) {
        float2 o2 = __half22float2(*(const __half2*)&op[j]);
        float2 g2 = __half22float2(*(const __half2*)&gp[j]);
        float sg0 = 1.f / (1.f + __expf(-g2.x));
        float sg1 = 1.f / (1.f + __expf(-g2.y));
        t[2*j]   = o2.x * sg0 + xv[2*j];
        t[2*j+1] = o2.y * sg1 + xv[2*j+1];
        s += t[2*j] + t[2*j+1];
        s2 += t[2*j]*t[2*j] + t[2*j+1]*t[2*j+1];
    }
    float mean, var; warp_meanvar(s, s2, mean, var);
    float rs = rsqrtf(var + EPS_);
    float4 gr0 = ((const float4*)gr)[lane*2], gr1 = ((const float4*)gr)[lane*2+1];
    float4 br0 = ((const float4*)br)[lane*2], br1 = ((const float4*)br)[lane*2+1];
    float grv[8] = {gr0.x, gr0.y, gr0.z, gr0.w, gr1.x, gr1.y, gr1.z, gr1.w};
    float brv[8] = {br0.x, br0.y, br0.z, br0.w, br1.x, br1.y, br1.z, br1.w};
    uint32_t outv[4];
    #pragma unroll
    for (int j = 0; j < 4; j++)
        outv[j] = pack2((t[2*j+1]-mean)*rs*grv[2*j+1]+brv[2*j+1],
                        (t[2*j]  -mean)*rs*grv[2*j]  +brv[2*j]);
    *(uint4*)(g_yh + (size_t)m * (H_ * E_) + h * E_ + lane * 8) = *(uint4*)outv;
}

// ---------------- K5: output projection (HMMA) + bias + residual ------------
__global__ void __launch_bounds__(256, 1) outproj_h_k(
    const float* __restrict__ out_b, const float* __restrict__ x)
{
    extern __shared__ char smem[];
    const int m0 = blockIdx.x * 128;
    const int tid = threadIdx.x, lane = tid & 31, warp = tid >> 5;
    const int wm = warp & 3, wn = warp >> 2;
    const __half* A = g_yh + (size_t)m0 * (H_ * E_);
    float acc[2][16][4];
    hgemm_main(A, H_ * E_, g_w1h, 16, smem, acc);

    #pragma unroll
    for (int mi = 0; mi < 2; mi++){
        int r0 = m0 + wm * 32 + mi * 16 + (lane >> 2), r1 = r0 + 8;
        #pragma unroll
        for (int nb = 0; nb < 8; nb++)
            #pragma unroll
            for (int t2 = 0; t2 < 2; t2++){
                int col = wn * 128 + nb * 16 + t2 * 8 + (lane & 3) * 2;
                const float* a = acc[mi][nb * 2 + t2];
                float b0 = out_b[col], b1 = out_b[col + 1];
                float2 x0 = *(const float2*)&x[(size_t)r0 * D_ + col];
                float2 x1 = *(const float2*)&x[(size_t)r1 * D_ + col];
                *(float2*)&g_z[(size_t)r0 * E_ + col] = make_float2(a[0] + b0 + x0.x, a[1] + b1 + x0.y);
                *(float2*)&g_z[(size_t)r1 * E_ + col] = make_float2(a[2] + b0 + x1.x, a[3] + b1 + x1.y);
            }
    }
}

// ---------------- K6: final LN * mask (warp per row) -------------------------
__global__ void __launch_bounds__(256) final_k(const float* __restrict__ mask,
                        const float* __restrict__ go, const float* __restrict__ bo,
                        float* __restrict__ out)
{
    int row = blockIdx.x * 8 + (threadIdx.x >> 5);
    int lane = threadIdx.x & 31;
    const float4* zr = (const float4*)(g_z + (size_t)row * E_) + lane * 2;
    float4 v0 = zr[0], v1 = zr[1];
    float s  = v0.x + v0.y + v0.z + v0.w + v1.x + v1.y + v1.z + v1.w;
    float s2 = v0.x*v0.x + v0.y*v0.y + v0.z*v0.z + v0.w*v0.w
             + v1.x*v1.x + v1.y*v1.y + v1.z*v1.z + v1.w*v1.w;
    float mean, var; warp_meanvar(s, s2, mean, var);
    float rs = rsqrtf(var + EPS_);
    float mv = (mask[row] == PADV) ? 0.f : 1.f;
    float4 g0 = ((const float4*)go)[lane*2], g1 = ((const float4*)go)[lane*2+1];
    float4 b0 = ((const float4*)bo)[lane*2], b1 = ((const float4*)bo)[lane*2+1];
    float4 r0, r1;
    r0.x = ((v0.x-mean)*rs*g0.x+b0.x)*mv; r0.y = ((v0.y-mean)*rs*g0.y+b0.y)*mv;
    r0.z = ((v0.z-mean)*rs*g0.z+b0.z)*mv; r0.w = ((v0.w-mean)*rs*g0.w+b0.w)*mv;
    r1.x = ((v1.x-mean)*rs*g1.x+b1.x)*mv; r1.y = ((v1.y-mean)*rs*g1.y+b1.y)*mv;
    r1.z = ((v1.z-mean)*rs*g1.z+b1.z)*mv; r1.w = ((v1.w-mean)*rs*g1.w+b1.w)*mv;
    float4* orow = (float4*)(out + (size_t)row * E_) + lane * 2;
    orow[0] = r0; orow[1] = r1;
}

// ---------------- launch ------------------------------------------------------
extern "C" void kernel_launch(void* const* d_in, const int* in_sizes, int n_in,
                              void* d_out, int out_size)
{
    (void)in_sizes; (void)n_in; (void)out_size;
    const float* x     = (const float*)d_in[0];
    const float* mask  = (const float*)d_in[1];
    const float* Wq    = (const float*)d_in[2];
    const float* Wk    = (const float*)d_in[3];
    const float* Wv    = (const float*)d_in[4];
    const float* Wg    = (const float*)d_in[5];
    const float* out_w = (const float*)d_in[6];
    const float* out_b = (const float*)d_in[7];
    const float* g_in  = (const float*)d_in[8];
    const float* b_in  = (const float*)d_in[9];
    const float* g_res = (const float*)d_in[10];
    const float* b_res = (const float*)d_in[11];
    const float* g_out = (const float*)d_in[12];
    const float* b_out = (const float*)d_in[13];
    float* out = (float*)d_out;

    cudaFuncSetAttribute(attn_mma_k,  cudaFuncAttributeMaxDynamicSharedMemorySize, AT_SMEM);
    cudaFuncSetAttribute(qkvg_h_k,    cudaFuncAttributeMaxDynamicSharedMemorySize, HG_SMEM);
    cudaFuncSetAttribute(outproj_h_k, cudaFuncAttributeMaxDynamicSharedMemorySize, HG_SMEM);

    ln_in_k<<<M_ / 8, 256>>>(x, g_in, b_in);
    wconv_k<<<dim3(H_ * D_ * E_ / 1024, 5), 256>>>(Wq, Wk, Wv, Wg, out_w);

    dim3 g2(M_ / 128, HB_);                    // (64, 16)
    qkvg_h_k<<<g2, 256, HG_SMEM>>>();

    dim3 g3(N_ / 128, HB_);                    // (16, 16)
    attn_mma_k<<<g3, 256, AT_SMEM>>>(mask);

    epi_k<<<M_ * H_ / 8, 256>>>(x, g_res, b_res);

    outproj_h_k<<<M_ / 128, 256, HG_SMEM>>>(out_b, x);

    final_k<<<M_ / 8, 256>>>(mask, g_out, b_out, out);
}